// round 2
// baseline (speedup 1.0000x reference)
#include <cuda_runtime.h>
#include <math.h>

#define BB 8
#define SS 1024
#define EE 1024
#define HH 16
#define DD 64
#define LL 2
#define MROWS (BB*SS)              // 8192
#define OUT_MAIN (BB*SS*EE)        // 8388608
#define OFF_PROBS OUT_MAIN
#define OFF_MODE  (OUT_MAIN + 8)
#define OFF_MEAN  (OUT_MAIN + 16)

// ---------------- scratch (device globals; no allocation allowed) ------------
__device__ float g_bufA[MROWS * 4096];   // qkv (8192x3072) / proj / ffn hidden (8192x4096)
__device__ float g_bufB[MROWS * EE];     // attention out / ffn2 out
__device__ float g_bufT[MROWS * EE];     // t (post layer)
__device__ float g_bufT1[MROWS * EE];    // t1 (post LN1)
__device__ float g_bufFast[MROWS * EE];  // fast path
__device__ float g_pooled[BB * EE];

__device__ __forceinline__ float gelu_exact(float v) {
    return 0.5f * v * (1.0f + erff(v * 0.7071067811865476f));
}

// ---------------- GEMM: C[M,N] = A[M,K] @ B[N,K]^T  (both row-major) ---------
// 128x128 tile, 256 threads, 8x8 per thread. M,N multiples of 128, K of 8.
template<int EPI>   // 0 = none, 1 = exact gelu
__global__ __launch_bounds__(256) void gemm_nt(const float* __restrict__ A,
                                               const float* __restrict__ Bm,
                                               float* __restrict__ C,
                                               int Mdim, int Ndim, int K) {
    __shared__ float As[8][128];
    __shared__ float Bs[8][128];
    int tid = threadIdx.x;
    int tx = tid & 15, ty = tid >> 4;
    const float* Ab = A  + (size_t)blockIdx.y * 128 * K;
    const float* Bb = Bm + (size_t)blockIdx.x * 128 * K;
    int lr = tid >> 1;          // row within tile (0..127)
    int lc = (tid & 1) * 4;     // k offset (0 or 4)

    float acc[8][8];
    #pragma unroll
    for (int i = 0; i < 8; i++)
        #pragma unroll
        for (int j = 0; j < 8; j++) acc[i][j] = 0.0f;

    for (int k0 = 0; k0 < K; k0 += 8) {
        float4 av = *(const float4*)(Ab + (size_t)lr * K + k0 + lc);
        float4 bv = *(const float4*)(Bb + (size_t)lr * K + k0 + lc);
        __syncthreads();   // protect previous iteration's reads
        As[lc+0][lr] = av.x; As[lc+1][lr] = av.y; As[lc+2][lr] = av.z; As[lc+3][lr] = av.w;
        Bs[lc+0][lr] = bv.x; Bs[lc+1][lr] = bv.y; Bs[lc+2][lr] = bv.z; Bs[lc+3][lr] = bv.w;
        __syncthreads();
        #pragma unroll
        for (int kk = 0; kk < 8; kk++) {
            float a[8], b[8];
            *(float4*)(a)     = *(const float4*)(&As[kk][ty*8]);
            *(float4*)(a + 4) = *(const float4*)(&As[kk][ty*8 + 4]);
            *(float4*)(b)     = *(const float4*)(&Bs[kk][tx*8]);
            *(float4*)(b + 4) = *(const float4*)(&Bs[kk][tx*8 + 4]);
            #pragma unroll
            for (int i = 0; i < 8; i++)
                #pragma unroll
                for (int j = 0; j < 8; j++)
                    acc[i][j] = fmaf(a[i], b[j], acc[i][j]);
        }
    }
    #pragma unroll
    for (int i = 0; i < 8; i++) {
        int row = blockIdx.y * 128 + ty * 8 + i;
        float* Cr = C + (size_t)row * Ndim + blockIdx.x * 128 + tx * 8;
        float4 o0, o1;
        if (EPI == 1) {
            o0.x = gelu_exact(acc[i][0]); o0.y = gelu_exact(acc[i][1]);
            o0.z = gelu_exact(acc[i][2]); o0.w = gelu_exact(acc[i][3]);
            o1.x = gelu_exact(acc[i][4]); o1.y = gelu_exact(acc[i][5]);
            o1.z = gelu_exact(acc[i][6]); o1.w = gelu_exact(acc[i][7]);
        } else {
            o0.x = acc[i][0]; o0.y = acc[i][1]; o0.z = acc[i][2]; o0.w = acc[i][3];
            o1.x = acc[i][4]; o1.y = acc[i][5]; o1.z = acc[i][6]; o1.w = acc[i][7];
        }
        *(float4*)(Cr)     = o0;
        *(float4*)(Cr + 4) = o1;
    }
}

// ---------------- Flash attention: qkv[B,S,3E] -> out[B,S,E] -----------------
// grid (S/64, H, B), 256 threads. Q tile 64 rows, KV tiles of 32, online softmax.
__global__ __launch_bounds__(256) void attn_kernel(const float* __restrict__ qkv,
                                                   float* __restrict__ out) {
    __shared__ float Qs[64][68];   // [d][r]
    __shared__ float Ks[64][36];   // [d][c]
    __shared__ float Vs[32][64];   // [c][d]
    __shared__ float Ps[64][33];   // scores / probs [r][c]
    __shared__ float rmax[64], rsum[64], ralpha[64];

    int qt = blockIdx.x, h = blockIdx.y, b = blockIdx.z;
    int tid = threadIdx.x;
    int tx = tid & 15, ty = tid >> 4;
    const int RS = 3 * EE;
    const float* base = qkv + (size_t)b * SS * RS + h * DD;

    for (int i = tid; i < 64 * 64; i += 256) {
        int r = i >> 6, d = i & 63;
        Qs[d][r] = base[(size_t)(qt * 64 + r) * RS + d] * 0.125f;  // 1/sqrt(64)
    }
    if (tid < 64) { rmax[tid] = -1e30f; rsum[tid] = 0.0f; }

    float o[4][4];
    #pragma unroll
    for (int i = 0; i < 4; i++)
        #pragma unroll
        for (int j = 0; j < 4; j++) o[i][j] = 0.0f;

    int r0 = ty * 4;
    __syncthreads();

    for (int kv0 = 0; kv0 < SS; kv0 += 32) {
        for (int i = tid; i < 32 * 64; i += 256) {
            int c = i >> 6, d = i & 63;
            Ks[d][c] = base[(size_t)(kv0 + c) * RS + EE + d];
            Vs[c][d] = base[(size_t)(kv0 + c) * RS + 2 * EE + d];
        }
        __syncthreads();

        // scores: rows r0..r0+3, cols c0..c0+1
        int c0 = tx * 2;
        float sacc[4][2];
        #pragma unroll
        for (int i = 0; i < 4; i++) { sacc[i][0] = 0.0f; sacc[i][1] = 0.0f; }
        #pragma unroll 8
        for (int d = 0; d < 64; d++) {
            float4 q4 = *(const float4*)(&Qs[d][r0]);
            float2 k2 = *(const float2*)(&Ks[d][c0]);
            sacc[0][0] = fmaf(q4.x, k2.x, sacc[0][0]);
            sacc[0][1] = fmaf(q4.x, k2.y, sacc[0][1]);
            sacc[1][0] = fmaf(q4.y, k2.x, sacc[1][0]);
            sacc[1][1] = fmaf(q4.y, k2.y, sacc[1][1]);
            sacc[2][0] = fmaf(q4.z, k2.x, sacc[2][0]);
            sacc[2][1] = fmaf(q4.z, k2.y, sacc[2][1]);
            sacc[3][0] = fmaf(q4.w, k2.x, sacc[3][0]);
            sacc[3][1] = fmaf(q4.w, k2.y, sacc[3][1]);
        }
        #pragma unroll
        for (int i = 0; i < 4; i++) {
            Ps[r0 + i][c0]     = sacc[i][0];
            Ps[r0 + i][c0 + 1] = sacc[i][1];
        }
        __syncthreads();

        // online softmax (one thread per row)
        if (tid < 64) {
            int r = tid;
            float mold = rmax[r];
            float mt = mold;
            #pragma unroll
            for (int c = 0; c < 32; c++) mt = fmaxf(mt, Ps[r][c]);
            float alpha = __expf(mold - mt);
            float sl = 0.0f;
            #pragma unroll
            for (int c = 0; c < 32; c++) {
                float p = __expf(Ps[r][c] - mt);
                Ps[r][c] = p;
                sl += p;
            }
            rmax[r] = mt; ralpha[r] = alpha;
            rsum[r] = rsum[r] * alpha + sl;
        }
        __syncthreads();

        // rescale and accumulate P @ V : rows r0.., cols d0..
        int d0 = tx * 4;
        #pragma unroll
        for (int i = 0; i < 4; i++) {
            float al = ralpha[r0 + i];
            o[i][0] *= al; o[i][1] *= al; o[i][2] *= al; o[i][3] *= al;
        }
        #pragma unroll
        for (int kk = 0; kk < 32; kk++) {
            float4 v4 = *(const float4*)(&Vs[kk][d0]);
            #pragma unroll
            for (int i = 0; i < 4; i++) {
                float p = Ps[r0 + i][kk];
                o[i][0] = fmaf(p, v4.x, o[i][0]);
                o[i][1] = fmaf(p, v4.y, o[i][1]);
                o[i][2] = fmaf(p, v4.z, o[i][2]);
                o[i][3] = fmaf(p, v4.w, o[i][3]);
            }
        }
        __syncthreads();
    }

    int d0 = tx * 4;
    #pragma unroll
    for (int i = 0; i < 4; i++) {
        float inv = 1.0f / rsum[r0 + i];
        float4 res;
        res.x = o[i][0] * inv; res.y = o[i][1] * inv;
        res.z = o[i][2] * inv; res.w = o[i][3] * inv;
        *(float4*)(out + ((size_t)b * SS + qt * 64 + r0 + i) * EE + h * DD + d0) = res;
    }
}

// ---------------- y = LN(a + b) * g + beta, one block per row (E=1024) -------
__global__ __launch_bounds__(256) void add_ln_kernel(const float* __restrict__ a,
                                                     const float* __restrict__ bsrc,
                                                     const float* __restrict__ g,
                                                     const float* __restrict__ beta,
                                                     float* __restrict__ y) {
    int row = blockIdx.x;
    int tid = threadIdx.x;
    const float* ar = a + (size_t)row * EE;
    const float* br = bsrc + (size_t)row * EE;
    float v[4];
    float s = 0.0f, s2 = 0.0f;
    #pragma unroll
    for (int k = 0; k < 4; k++) {
        float t = ar[tid + 256 * k] + br[tid + 256 * k];
        v[k] = t; s += t; s2 += t * t;
    }
    __shared__ float red[18];
    #pragma unroll
    for (int off = 16; off; off >>= 1) {
        s  += __shfl_xor_sync(0xffffffffu, s,  off);
        s2 += __shfl_xor_sync(0xffffffffu, s2, off);
    }
    int wid = tid >> 5, lid = tid & 31;
    if (lid == 0) { red[wid] = s; red[wid + 8] = s2; }
    __syncthreads();
    if (tid < 32) {
        float a1 = (tid < 8) ? red[tid] : 0.0f;
        float a2 = (tid < 8) ? red[tid + 8] : 0.0f;
        #pragma unroll
        for (int off = 4; off; off >>= 1) {
            a1 += __shfl_xor_sync(0xffffffffu, a1, off);
            a2 += __shfl_xor_sync(0xffffffffu, a2, off);
        }
        if (tid == 0) { red[16] = a1; red[17] = a2; }
    }
    __syncthreads();
    float mu = red[16] * (1.0f / EE);
    float var = red[17] * (1.0f / EE) - mu * mu;
    float rs = rsqrtf(var + 1e-5f);
    float* yr = y + (size_t)row * EE;
    #pragma unroll
    for (int k = 0; k < 4; k++) {
        int c = tid + 256 * k;
        yr[c] = (v[k] - mu) * rs * g[c] + beta[c];
    }
}

// ---------------- mean-pool over S: x[B,S,E] -> pooled[B,E] ------------------
__global__ __launch_bounds__(256) void pool_kernel(const float* __restrict__ x,
                                                   float* __restrict__ pooled) {
    int idx = blockIdx.x * 256 + threadIdx.x;    // 8192 threads
    int b = idx >> 10, e = idx & 1023;
    const float* p = x + (size_t)b * SS * EE + e;
    float s = 0.0f;
    for (int sI = 0; sI < SS; sI++) s += p[(size_t)sI * EE];
    pooled[idx] = s * (1.0f / SS);
}

// ---------------- complexity estimator: probs + mode into out tail -----------
__global__ __launch_bounds__(256) void ce_kernel(const float* __restrict__ pooled,
                                                 const float* __restrict__ w1,
                                                 const float* __restrict__ b1,
                                                 const float* __restrict__ w2,
                                                 const float* __restrict__ b2,
                                                 float* __restrict__ out) {
    int b = blockIdx.x, j = threadIdx.x;  // 256 threads = E/4 hidden units
    const float* p = pooled + b * EE;
    const float* w = w1 + (size_t)j * EE;
    float s = b1[j];
    for (int k = 0; k < EE; k++) s = fmaf(p[k], w[k], s);
    float h = fmaxf(s, 0.0f);
    __shared__ float red[256];
    red[j] = h * w2[j];
    __syncthreads();
    for (int off = 128; off; off >>= 1) {
        if (j < off) red[j] += red[j + off];
        __syncthreads();
    }
    if (j == 0) {
        float logit = red[0] + b2[0];
        float prob = 1.0f / (1.0f + expf(-logit));
        out[OFF_PROBS + b] = prob;
        out[OFF_MODE + b] = (prob > 0.5f) ? 1.0f : 0.0f;
    }
}

// ---------------- select + mean(mode) ----------------------------------------
__global__ __launch_bounds__(256) void finalize_kernel(const float* __restrict__ t,
                                                       const float* __restrict__ f,
                                                       float* __restrict__ out) {
    size_t i = (size_t)blockIdx.x * 256 + threadIdx.x;  // float4 index, 2097152 total
    int b = (int)((i * 4) >> 20);                       // S*E = 1M per batch
    float m = out[OFF_MODE + b];
    float4 r = (m > 0.5f) ? ((const float4*)t)[i] : ((const float4*)f)[i];
    ((float4*)out)[i] = r;
    if (i == 0) {
        float sAcc = 0.0f;
        for (int k = 0; k < 8; k++) sAcc += out[OFF_MODE + k];
        out[OFF_MEAN] = sAcc * 0.125f;
    }
}

// -----------------------------------------------------------------------------
extern "C" void kernel_launch(void* const* d_in, const int* in_sizes, int n_in,
                              void* d_out, int out_size) {
    const float* x      = (const float*)d_in[0];
    const float* w_in   = (const float*)d_in[1];
    const float* w_out  = (const float*)d_in[2];
    const float* ffn_w1 = (const float*)d_in[3];
    const float* ffn_w2 = (const float*)d_in[4];
    const float* ln1_g  = (const float*)d_in[5];
    const float* ln1_b  = (const float*)d_in[6];
    const float* ln2_g  = (const float*)d_in[7];
    const float* ln2_b  = (const float*)d_in[8];
    const float* ce_w1  = (const float*)d_in[9];
    const float* ce_b1  = (const float*)d_in[10];
    const float* ce_w2  = (const float*)d_in[11];
    const float* ce_b2  = (const float*)d_in[12];
    const float* fast_w = (const float*)d_in[13];
    float* out = (float*)d_out;

    float *bufA, *bufB, *bufT, *bufT1, *bufFast, *pooled;
    cudaGetSymbolAddress((void**)&bufA, g_bufA);
    cudaGetSymbolAddress((void**)&bufB, g_bufB);
    cudaGetSymbolAddress((void**)&bufT, g_bufT);
    cudaGetSymbolAddress((void**)&bufT1, g_bufT1);
    cudaGetSymbolAddress((void**)&bufFast, g_bufFast);
    cudaGetSymbolAddress((void**)&pooled, g_pooled);

    // complexity estimator -> probs, mode in out tail
    pool_kernel<<<(BB * EE) / 256, 256>>>(x, pooled);
    ce_kernel<<<BB, 256>>>(pooled, ce_w1, ce_b1, ce_w2, ce_b2, out);

    // fast path: gelu(x @ fast_w^T)
    gemm_nt<1><<<dim3(EE / 128, MROWS / 128), 256>>>(x, fast_w, bufFast, MROWS, EE, EE);

    // thinking path
    const float* tin = x;
    for (int l = 0; l < LL; l++) {
        gemm_nt<0><<<dim3(3 * EE / 128, MROWS / 128), 256>>>(
            tin, w_in + (size_t)l * 3 * EE * EE, bufA, MROWS, 3 * EE, EE);
        attn_kernel<<<dim3(SS / 64, HH, BB), 256>>>(bufA, bufB);
        gemm_nt<0><<<dim3(EE / 128, MROWS / 128), 256>>>(
            bufB, w_out + (size_t)l * EE * EE, bufA, MROWS, EE, EE);
        add_ln_kernel<<<MROWS, 256>>>(tin, bufA, ln1_g + l * EE, ln1_b + l * EE, bufT1);
        gemm_nt<1><<<dim3(4 * EE / 128, MROWS / 128), 256>>>(
            bufT1, ffn_w1 + (size_t)l * 4 * EE * EE, bufA, MROWS, 4 * EE, EE);
        gemm_nt<0><<<dim3(EE / 128, MROWS / 128), 256>>>(
            bufA, ffn_w2 + (size_t)l * EE * 4 * EE, bufB, MROWS, EE, 4 * EE);
        add_ln_kernel<<<MROWS, 256>>>(bufT1, bufB, ln2_g + l * EE, ln2_b + l * EE, bufT);
        tin = bufT;
    }

    // out = where(mode, t, fast); also mean(mode)
    finalize_kernel<<<(MROWS * EE / 4) / 256, 256>>>(bufT, bufFast, out);
}

// round 4
// speedup vs baseline: 1.9558x; 1.9558x over previous
#include <cuda_runtime.h>
#include <cuda_bf16.h>
#include <math.h>
#include <stdint.h>

#define BB 8
#define SS 1024
#define EE 1024
#define HH 16
#define DD 64
#define LL 2
#define MROWS (BB*SS)              // 8192
#define OUT_MAIN (BB*SS*EE)        // 8388608
#define OFF_PROBS OUT_MAIN
#define OFF_MODE  (OUT_MAIN + 8)
#define OFF_MEAN  (OUT_MAIN + 16)

// ---------------- scratch (device globals; no allocation allowed) ------------
__device__ float g_bufA[MROWS * 4096];   // qkv (8192x3072) / ffn hidden (8192x4096) / proj
__device__ float g_bufB[MROWS * EE];     // attention out / ffn2 out
__device__ float g_bufT[MROWS * EE];     // t (post layer)
__device__ float g_bufT1[MROWS * EE];    // t1 (post LN1)
__device__ float g_bufFast[MROWS * EE];  // fast path
__device__ float g_pooled[BB * EE];

// bf16 split buffers
#define NW_TOTAL 26214400
#define OW_IN   0
#define OW_OUT  6291456
#define OW_F1   8388608
#define OW_F2   16777216
#define OW_FAST 25165824
__device__ __nv_bfloat16 g_wb_hi[NW_TOTAL];
__device__ __nv_bfloat16 g_wb_lo[NW_TOTAL];
__device__ __nv_bfloat16 g_act_hi[MROWS * 4096];
__device__ __nv_bfloat16 g_act_lo[MROWS * 4096];

__device__ __forceinline__ float gelu_exact(float v) {
    return 0.5f * v * (1.0f + erff(v * 0.7071067811865476f));
}

// =================== portable tensor-core primitives (sm_80+ PTX) ============
__device__ __forceinline__ uint32_t smem_u32(const void* p) {
    uint32_t a;
    asm("{ .reg .u64 t; cvta.to.shared.u64 t, %1; cvt.u32.u64 %0, t; }" : "=r"(a) : "l"(p));
    return a;
}
__device__ __forceinline__ void ldm_x4(uint32_t& r0, uint32_t& r1, uint32_t& r2, uint32_t& r3,
                                       uint32_t addr) {
    asm volatile("ldmatrix.sync.aligned.m8n8.x4.shared.b16 {%0,%1,%2,%3}, [%4];"
                 : "=r"(r0), "=r"(r1), "=r"(r2), "=r"(r3) : "r"(addr));
}
__device__ __forceinline__ void mma16816(float* c, uint32_t a0, uint32_t a1, uint32_t a2,
                                         uint32_t a3, uint32_t b0, uint32_t b1) {
    asm volatile(
        "mma.sync.aligned.m16n8k16.row.col.f32.bf16.bf16.f32 "
        "{%0,%1,%2,%3}, {%4,%5,%6,%7}, {%8,%9}, {%0,%1,%2,%3};"
        : "+f"(c[0]), "+f"(c[1]), "+f"(c[2]), "+f"(c[3])
        : "r"(a0), "r"(a1), "r"(a2), "r"(a3), "r"(b0), "r"(b1));
}
__device__ __forceinline__ void cp16(uint32_t saddr, const void* g) {
    asm volatile("cp.async.cg.shared.global [%0], [%1], 16;" :: "r"(saddr), "l"(g));
}
#define CP_COMMIT() asm volatile("cp.async.commit_group;" ::: "memory")
#define CP_WAIT(N)  asm volatile("cp.async.wait_group %0;" :: "n"(N) : "memory")

// =================== mma.sync GEMM: C[M,N] = A[M,K] @ B[N,K]^T ===============
// A,B as bf16 hi/lo splits (row-major, K contiguous). 128x128 block, 8 warps
// (2M x 4N), warp tile 64x32, K-chunk 32, 3 mma per fragment (hh + hl + lh).
// smem rows padded to 40 bf16 (80B): conflict-free ldmatrix.
#define TIL   10240                     // 128 rows * 80B
#define STAGE (4 * TIL)                 // Ahi, Alo, Bhi, Blo
#define SMT   (2 * STAGE)               // 81920

__device__ __forceinline__ void copy_tile_async(uint32_t sdst, const __nv_bfloat16* __restrict__ g,
                                                int row0, int K, int k0, int tid) {
    #pragma unroll
    for (int i = 0; i < 2; i++) {
        int idx = tid + i * 256;        // 0..511
        int r = idx >> 2, c4 = idx & 3;
        cp16(sdst + r * 80 + c4 * 16, g + (size_t)(row0 + r) * K + k0 + c4 * 8);
    }
}

template<int EPI>   // 0 = none, 1 = exact gelu
__global__ __launch_bounds__(256) void mma_gemm(
        const __nv_bfloat16* __restrict__ Ahi, const __nv_bfloat16* __restrict__ Alo,
        const __nv_bfloat16* __restrict__ Bhi, const __nv_bfloat16* __restrict__ Blo,
        float* __restrict__ C, int N, int K) {
    extern __shared__ __align__(128) char smem[];
    uint32_t sb = smem_u32(smem);
    int tid = threadIdx.x, lane = tid & 31, warp = tid >> 5;
    int wm = warp & 1, wn = warp >> 1;            // 2 M-warps x 4 N-warps
    int rowB = blockIdx.y * 128, colB = blockIdx.x * 128;

    // ldmatrix address components (element offsets within a tile)
    int aRow = wm * 64 + (lane & 15);
    int aK   = (lane >> 4) * 8;
    uint32_t aOff = (uint32_t)(aRow * 80 + aK * 2);
    int bRow = wn * 32 + ((lane >> 4) << 3) + (lane & 7);
    int bK   = ((lane >> 3) & 1) * 8;
    uint32_t bOff = (uint32_t)(bRow * 80 + bK * 2);

    float acc[4][4][4];
    #pragma unroll
    for (int i = 0; i < 4; i++)
        #pragma unroll
        for (int j = 0; j < 4; j++)
            #pragma unroll
            for (int k = 0; k < 4; k++) acc[i][j][k] = 0.0f;

    int nch = K >> 5;
    // prologue: chunk 0
    {
        uint32_t s0 = sb;
        copy_tile_async(s0 + 0 * TIL, Ahi, rowB, K, 0, tid);
        copy_tile_async(s0 + 1 * TIL, Alo, rowB, K, 0, tid);
        copy_tile_async(s0 + 2 * TIL, Bhi, colB, K, 0, tid);
        copy_tile_async(s0 + 3 * TIL, Blo, colB, K, 0, tid);
        CP_COMMIT();
    }

    for (int c = 0; c < nch; c++) {
        if (c + 1 < nch) {
            uint32_t sn = sb + ((c + 1) & 1) * STAGE;
            int k0 = (c + 1) * 32;
            copy_tile_async(sn + 0 * TIL, Ahi, rowB, K, k0, tid);
            copy_tile_async(sn + 1 * TIL, Alo, rowB, K, k0, tid);
            copy_tile_async(sn + 2 * TIL, Bhi, colB, K, k0, tid);
            copy_tile_async(sn + 3 * TIL, Blo, colB, K, k0, tid);
            CP_COMMIT();
            CP_WAIT(1);
        } else {
            CP_WAIT(0);
        }
        __syncthreads();

        uint32_t ss = sb + (c & 1) * STAGE;
        uint32_t sAh = ss + aOff, sAl = ss + TIL + aOff;
        uint32_t sBh = ss + 2 * TIL + bOff, sBl = ss + 3 * TIL + bOff;

        #pragma unroll
        for (int k16 = 0; k16 < 2; k16++) {
            uint32_t kb = k16 * 32;   // 16 elems * 2B
            uint32_t ah[4][4], al[4][4], bh[2][4], bl[2][4];
            #pragma unroll
            for (int mt = 0; mt < 4; mt++) {
                uint32_t off = (uint32_t)(mt * 16 * 80) + kb;
                ldm_x4(ah[mt][0], ah[mt][1], ah[mt][2], ah[mt][3], sAh + off);
                ldm_x4(al[mt][0], al[mt][1], al[mt][2], al[mt][3], sAl + off);
            }
            #pragma unroll
            for (int nh = 0; nh < 2; nh++) {
                uint32_t off = (uint32_t)(nh * 16 * 80) + kb;
                ldm_x4(bh[nh][0], bh[nh][1], bh[nh][2], bh[nh][3], sBh + off);
                ldm_x4(bl[nh][0], bl[nh][1], bl[nh][2], bl[nh][3], sBl + off);
            }
            #pragma unroll
            for (int mt = 0; mt < 4; mt++)
                #pragma unroll
                for (int nt = 0; nt < 4; nt++) {
                    int nh = nt >> 1, o = (nt & 1) * 2;
                    mma16816(acc[mt][nt], ah[mt][0], ah[mt][1], ah[mt][2], ah[mt][3],
                             bh[nh][o], bh[nh][o + 1]);
                    mma16816(acc[mt][nt], ah[mt][0], ah[mt][1], ah[mt][2], ah[mt][3],
                             bl[nh][o], bl[nh][o + 1]);
                    mma16816(acc[mt][nt], al[mt][0], al[mt][1], al[mt][2], al[mt][3],
                             bh[nh][o], bh[nh][o + 1]);
                }
        }
        __syncthreads();
    }

    // epilogue
    int r = lane >> 2, c2 = (lane & 3) * 2;
    int row0 = rowB + wm * 64, col0 = colB + wn * 32;
    #pragma unroll
    for (int mt = 0; mt < 4; mt++)
        #pragma unroll
        for (int nt = 0; nt < 4; nt++) {
            float v0 = acc[mt][nt][0], v1 = acc[mt][nt][1];
            float v2 = acc[mt][nt][2], v3 = acc[mt][nt][3];
            if (EPI == 1) {
                v0 = gelu_exact(v0); v1 = gelu_exact(v1);
                v2 = gelu_exact(v2); v3 = gelu_exact(v3);
            }
            int row = row0 + mt * 16 + r, col = col0 + nt * 8 + c2;
            float2 p0 = {v0, v1}, p1 = {v2, v3};
            *(float2*)(C + (size_t)row * N + col) = p0;
            *(float2*)(C + (size_t)(row + 8) * N + col) = p1;
        }
}

// ---------------- fp32 -> bf16 hi/lo split -----------------------------------
__global__ __launch_bounds__(256) void split_kernel(const float* __restrict__ in,
                                                    __nv_bfloat16* __restrict__ hi,
                                                    __nv_bfloat16* __restrict__ lo,
                                                    int n4) {
    int i = blockIdx.x * 256 + threadIdx.x;
    if (i >= n4) return;
    float4 v = ((const float4*)in)[i];
    float x[4] = {v.x, v.y, v.z, v.w};
    uint32_t hw[4], lw[4];
    #pragma unroll
    for (int k = 0; k < 4; k++) {
        __nv_bfloat16 h = __float2bfloat16(x[k]);
        float rr = x[k] - __bfloat162float(h);
        __nv_bfloat16 l = __float2bfloat16(rr);
        hw[k] = (uint32_t)__bfloat16_as_ushort(h);
        lw[k] = (uint32_t)__bfloat16_as_ushort(l);
    }
    uint2 ho, loo;
    ho.x  = hw[0] | (hw[1] << 16);  ho.y  = hw[2] | (hw[3] << 16);
    loo.x = lw[0] | (lw[1] << 16);  loo.y = lw[2] | (lw[3] << 16);
    ((uint2*)hi)[i] = ho;
    ((uint2*)lo)[i] = loo;
}

// ---------------- Flash attention: qkv[B,S,3E] -> out[B,S,E] -----------------
__global__ __launch_bounds__(256) void attn_kernel(const float* __restrict__ qkv,
                                                   float* __restrict__ out) {
    __shared__ float Qs[64][68];   // [d][r]
    __shared__ float Ks[64][36];   // [d][c]
    __shared__ float Vs[32][64];   // [c][d]
    __shared__ float Ps[64][33];   // scores / probs [r][c]
    __shared__ float rmax[64], rsum[64], ralpha[64];

    int qt = blockIdx.x, h = blockIdx.y, b = blockIdx.z;
    int tid = threadIdx.x;
    int tx = tid & 15, ty = tid >> 4;
    const int RS = 3 * EE;
    const float* base = qkv + (size_t)b * SS * RS + h * DD;

    for (int i = tid; i < 64 * 64; i += 256) {
        int r = i >> 6, d = i & 63;
        Qs[d][r] = base[(size_t)(qt * 64 + r) * RS + d] * 0.125f;
    }
    if (tid < 64) { rmax[tid] = -1e30f; rsum[tid] = 0.0f; }

    float o[4][4];
    #pragma unroll
    for (int i = 0; i < 4; i++)
        #pragma unroll
        for (int j = 0; j < 4; j++) o[i][j] = 0.0f;

    int r0 = ty * 4;
    __syncthreads();

    for (int kv0 = 0; kv0 < SS; kv0 += 32) {
        for (int i = tid; i < 32 * 64; i += 256) {
            int c = i >> 6, d = i & 63;
            Ks[d][c] = base[(size_t)(kv0 + c) * RS + EE + d];
            Vs[c][d] = base[(size_t)(kv0 + c) * RS + 2 * EE + d];
        }
        __syncthreads();

        int c0 = tx * 2;
        float sacc[4][2];
        #pragma unroll
        for (int i = 0; i < 4; i++) { sacc[i][0] = 0.0f; sacc[i][1] = 0.0f; }
        #pragma unroll 8
        for (int d = 0; d < 64; d++) {
            float4 q4 = *(const float4*)(&Qs[d][r0]);
            float2 k2 = *(const float2*)(&Ks[d][c0]);
            sacc[0][0] = fmaf(q4.x, k2.x, sacc[0][0]);
            sacc[0][1] = fmaf(q4.x, k2.y, sacc[0][1]);
            sacc[1][0] = fmaf(q4.y, k2.x, sacc[1][0]);
            sacc[1][1] = fmaf(q4.y, k2.y, sacc[1][1]);
            sacc[2][0] = fmaf(q4.z, k2.x, sacc[2][0]);
            sacc[2][1] = fmaf(q4.z, k2.y, sacc[2][1]);
            sacc[3][0] = fmaf(q4.w, k2.x, sacc[3][0]);
            sacc[3][1] = fmaf(q4.w, k2.y, sacc[3][1]);
        }
        #pragma unroll
        for (int i = 0; i < 4; i++) {
            Ps[r0 + i][c0]     = sacc[i][0];
            Ps[r0 + i][c0 + 1] = sacc[i][1];
        }
        __syncthreads();

        if (tid < 64) {
            int r = tid;
            float mold = rmax[r];
            float mt = mold;
            #pragma unroll
            for (int c = 0; c < 32; c++) mt = fmaxf(mt, Ps[r][c]);
            float alpha = __expf(mold - mt);
            float sl = 0.0f;
            #pragma unroll
            for (int c = 0; c < 32; c++) {
                float p = __expf(Ps[r][c] - mt);
                Ps[r][c] = p;
                sl += p;
            }
            rmax[r] = mt; ralpha[r] = alpha;
            rsum[r] = rsum[r] * alpha + sl;
        }
        __syncthreads();

        int d0 = tx * 4;
        #pragma unroll
        for (int i = 0; i < 4; i++) {
            float al = ralpha[r0 + i];
            o[i][0] *= al; o[i][1] *= al; o[i][2] *= al; o[i][3] *= al;
        }
        #pragma unroll
        for (int kk = 0; kk < 32; kk++) {
            float4 v4 = *(const float4*)(&Vs[kk][d0]);
            #pragma unroll
            for (int i = 0; i < 4; i++) {
                float p = Ps[r0 + i][kk];
                o[i][0] = fmaf(p, v4.x, o[i][0]);
                o[i][1] = fmaf(p, v4.y, o[i][1]);
                o[i][2] = fmaf(p, v4.z, o[i][2]);
                o[i][3] = fmaf(p, v4.w, o[i][3]);
            }
        }
        __syncthreads();
    }

    int d0 = tx * 4;
    #pragma unroll
    for (int i = 0; i < 4; i++) {
        float inv = 1.0f / rsum[r0 + i];
        float4 res;
        res.x = o[i][0] * inv; res.y = o[i][1] * inv;
        res.z = o[i][2] * inv; res.w = o[i][3] * inv;
        *(float4*)(out + ((size_t)b * SS + qt * 64 + r0 + i) * EE + h * DD + d0) = res;
    }
}

// ---------------- y = LN(a + b) * g + beta -----------------------------------
__global__ __launch_bounds__(256) void add_ln_kernel(const float* __restrict__ a,
                                                     const float* __restrict__ bsrc,
                                                     const float* __restrict__ g,
                                                     const float* __restrict__ beta,
                                                     float* __restrict__ y) {
    int row = blockIdx.x;
    int tid = threadIdx.x;
    const float* ar = a + (size_t)row * EE;
    const float* br = bsrc + (size_t)row * EE;
    float v[4];
    float s = 0.0f, s2 = 0.0f;
    #pragma unroll
    for (int k = 0; k < 4; k++) {
        float t = ar[tid + 256 * k] + br[tid + 256 * k];
        v[k] = t; s += t; s2 += t * t;
    }
    __shared__ float red[18];
    #pragma unroll
    for (int off = 16; off; off >>= 1) {
        s  += __shfl_xor_sync(0xffffffffu, s,  off);
        s2 += __shfl_xor_sync(0xffffffffu, s2, off);
    }
    int wid = tid >> 5, lid = tid & 31;
    if (lid == 0) { red[wid] = s; red[wid + 8] = s2; }
    __syncthreads();
    if (tid < 32) {
        float a1 = (tid < 8) ? red[tid] : 0.0f;
        float a2 = (tid < 8) ? red[tid + 8] : 0.0f;
        #pragma unroll
        for (int off = 4; off; off >>= 1) {
            a1 += __shfl_xor_sync(0xffffffffu, a1, off);
            a2 += __shfl_xor_sync(0xffffffffu, a2, off);
        }
        if (tid == 0) { red[16] = a1; red[17] = a2; }
    }
    __syncthreads();
    float mu = red[16] * (1.0f / EE);
    float var = red[17] * (1.0f / EE) - mu * mu;
    float rs = rsqrtf(var + 1e-5f);
    float* yr = y + (size_t)row * EE;
    #pragma unroll
    for (int k = 0; k < 4; k++) {
        int c = tid + 256 * k;
        yr[c] = (v[k] - mu) * rs * g[c] + beta[c];
    }
}

// ---------------- mean-pool over S -------------------------------------------
__global__ __launch_bounds__(256) void pool_kernel(const float* __restrict__ x,
                                                   float* __restrict__ pooled) {
    int idx = blockIdx.x * 256 + threadIdx.x;
    int b = idx >> 10, e = idx & 1023;
    const float* p = x + (size_t)b * SS * EE + e;
    float s = 0.0f;
    for (int sI = 0; sI < SS; sI++) s += p[(size_t)sI * EE];
    pooled[idx] = s * (1.0f / SS);
}

// ---------------- complexity estimator ---------------------------------------
__global__ __launch_bounds__(256) void ce_kernel(const float* __restrict__ pooled,
                                                 const float* __restrict__ w1,
                                                 const float* __restrict__ b1,
                                                 const float* __restrict__ w2,
                                                 const float* __restrict__ b2,
                                                 float* __restrict__ out) {
    int b = blockIdx.x, j = threadIdx.x;
    const float* p = pooled + b * EE;
    const float* w = w1 + (size_t)j * EE;
    float s = b1[j];
    for (int k = 0; k < EE; k++) s = fmaf(p[k], w[k], s);
    float h = fmaxf(s, 0.0f);
    __shared__ float red[256];
    red[j] = h * w2[j];
    __syncthreads();
    for (int off = 128; off; off >>= 1) {
        if (j < off) red[j] += red[j + off];
        __syncthreads();
    }
    if (j == 0) {
        float logit = red[0] + b2[0];
        float prob = 1.0f / (1.0f + expf(-logit));
        out[OFF_PROBS + b] = prob;
        out[OFF_MODE + b] = (prob > 0.5f) ? 1.0f : 0.0f;
    }
}

// ---------------- select + mean(mode) ----------------------------------------
__global__ __launch_bounds__(256) void finalize_kernel(const float* __restrict__ t,
                                                       const float* __restrict__ f,
                                                       float* __restrict__ out) {
    size_t i = (size_t)blockIdx.x * 256 + threadIdx.x;
    int b = (int)((i * 4) >> 20);
    float m = out[OFF_MODE + b];
    float4 r = (m > 0.5f) ? ((const float4*)t)[i] : ((const float4*)f)[i];
    ((float4*)out)[i] = r;
    if (i == 0) {
        float sAcc = 0.0f;
        for (int k = 0; k < 8; k++) sAcc += out[OFF_MODE + k];
        out[OFF_MEAN] = sAcc * 0.125f;
    }
}

// -----------------------------------------------------------------------------
extern "C" void kernel_launch(void* const* d_in, const int* in_sizes, int n_in,
                              void* d_out, int out_size) {
    const float* x      = (const float*)d_in[0];
    const float* w_in   = (const float*)d_in[1];
    const float* w_out  = (const float*)d_in[2];
    const float* ffn_w1 = (const float*)d_in[3];
    const float* ffn_w2 = (const float*)d_in[4];
    const float* ln1_g  = (const float*)d_in[5];
    const float* ln1_b  = (const float*)d_in[6];
    const float* ln2_g  = (const float*)d_in[7];
    const float* ln2_b  = (const float*)d_in[8];
    const float* ce_w1  = (const float*)d_in[9];
    const float* ce_b1  = (const float*)d_in[10];
    const float* ce_w2  = (const float*)d_in[11];
    const float* ce_b2  = (const float*)d_in[12];
    const float* fast_w = (const float*)d_in[13];
    float* out = (float*)d_out;

    float *bufA, *bufB, *bufT, *bufT1, *bufFast, *pooled;
    __nv_bfloat16 *wbh, *wbl, *ah, *al;
    cudaGetSymbolAddress((void**)&bufA, g_bufA);
    cudaGetSymbolAddress((void**)&bufB, g_bufB);
    cudaGetSymbolAddress((void**)&bufT, g_bufT);
    cudaGetSymbolAddress((void**)&bufT1, g_bufT1);
    cudaGetSymbolAddress((void**)&bufFast, g_bufFast);
    cudaGetSymbolAddress((void**)&pooled, g_pooled);
    cudaGetSymbolAddress((void**)&wbh, g_wb_hi);
    cudaGetSymbolAddress((void**)&wbl, g_wb_lo);
    cudaGetSymbolAddress((void**)&ah, g_act_hi);
    cudaGetSymbolAddress((void**)&al, g_act_lo);

    cudaFuncSetAttribute(mma_gemm<0>, cudaFuncAttributeMaxDynamicSharedMemorySize, SMT);
    cudaFuncSetAttribute(mma_gemm<1>, cudaFuncAttributeMaxDynamicSharedMemorySize, SMT);

    // weight splits
    split_kernel<<<(2*3*EE*EE/4)/256, 256>>>(w_in,   wbh + OW_IN,   wbl + OW_IN,   2*3*EE*EE/4);
    split_kernel<<<(2*EE*EE/4)/256,   256>>>(w_out,  wbh + OW_OUT,  wbl + OW_OUT,  2*EE*EE/4);
    split_kernel<<<(2*4*EE*EE/4)/256, 256>>>(ffn_w1, wbh + OW_F1,   wbl + OW_F1,   2*4*EE*EE/4);
    split_kernel<<<(2*4*EE*EE/4)/256, 256>>>(ffn_w2, wbh + OW_F2,   wbl + OW_F2,   2*4*EE*EE/4);
    split_kernel<<<(EE*EE/4)/256,     256>>>(fast_w, wbh + OW_FAST, wbl + OW_FAST, EE*EE/4);

    // complexity estimator
    pool_kernel<<<(BB * EE) / 256, 256>>>(x, pooled);
    ce_kernel<<<BB, 256>>>(pooled, ce_w1, ce_b1, ce_w2, ce_b2, out);

    // split x (serves fast path + layer-0 qkv)
    split_kernel<<<(MROWS*EE/4)/256, 256>>>(x, ah, al, MROWS*EE/4);

    // fast path: gelu(x @ fast_w^T)
    mma_gemm<1><<<dim3(EE/128, MROWS/128), 256, SMT>>>(
        ah, al, wbh + OW_FAST, wbl + OW_FAST, bufFast, EE, EE);

    // thinking path
    const float* tin = x;
    for (int l = 0; l < LL; l++) {
        if (l > 0) split_kernel<<<(MROWS*EE/4)/256, 256>>>(tin, ah, al, MROWS*EE/4);
        mma_gemm<0><<<dim3(3*EE/128, MROWS/128), 256, SMT>>>(
            ah, al, wbh + OW_IN + (size_t)l*3*EE*EE, wbl + OW_IN + (size_t)l*3*EE*EE,
            bufA, 3*EE, EE);
        attn_kernel<<<dim3(SS/64, HH, BB), 256>>>(bufA, bufB);
        split_kernel<<<(MROWS*EE/4)/256, 256>>>(bufB, ah, al, MROWS*EE/4);
        mma_gemm<0><<<dim3(EE/128, MROWS/128), 256, SMT>>>(
            ah, al, wbh + OW_OUT + (size_t)l*EE*EE, wbl + OW_OUT + (size_t)l*EE*EE,
            bufA, EE, EE);
        add_ln_kernel<<<MROWS, 256>>>(tin, bufA, ln1_g + l*EE, ln1_b + l*EE, bufT1);
        split_kernel<<<(MROWS*EE/4)/256, 256>>>(bufT1, ah, al, MROWS*EE/4);
        mma_gemm<1><<<dim3(4*EE/128, MROWS/128), 256, SMT>>>(
            ah, al, wbh + OW_F1 + (size_t)l*4*EE*EE, wbl + OW_F1 + (size_t)l*4*EE*EE,
            bufA, 4*EE, EE);
        split_kernel<<<(MROWS*4*EE/4)/256, 256>>>(bufA, ah, al, MROWS*4*EE/4);
        mma_gemm<0><<<dim3(EE/128, MROWS/128), 256, SMT>>>(
            ah, al, wbh + OW_F2 + (size_t)l*4*EE*EE, wbl + OW_F2 + (size_t)l*4*EE*EE,
            bufB, EE, 4*EE);
        add_ln_kernel<<<MROWS, 256>>>(bufT1, bufB, ln2_g + l*EE, ln2_b + l*EE, bufT);
        tin = bufT;
    }

    // out = where(mode, t, fast); also mean(mode)
    finalize_kernel<<<(MROWS * EE / 4) / 256, 256>>>(bufT, bufFast, out);
}

// round 5
// speedup vs baseline: 2.6473x; 1.3536x over previous
#include <cuda_runtime.h>
#include <cuda_bf16.h>
#include <math.h>
#include <stdint.h>

#define BB 8
#define SS 1024
#define EE 1024
#define HH 16
#define DD 64
#define LL 2
#define MROWS (BB*SS)              // 8192
#define OUT_MAIN (BB*SS*EE)        // 8388608
#define OFF_PROBS OUT_MAIN
#define OFF_MODE  (OUT_MAIN + 8)
#define OFF_MEAN  (OUT_MAIN + 16)

// ---------------- scratch (device globals; no allocation allowed) ------------
__device__ float g_bufA[MROWS * EE];     // out-proj fp32
__device__ float g_bufB[MROWS * EE];     // ffn2 out fp32
__device__ float g_bufT[MROWS * EE];     // t (post layer)
__device__ float g_bufT1[MROWS * EE];    // t1 (post LN1)
__device__ float g_bufFast[MROWS * EE];  // fast path
__device__ float g_pooled[BB * EE];

// bf16 split buffers
#define NW_TOTAL 26214400
#define OW_IN   0
#define OW_OUT  6291456
#define OW_F1   8388608
#define OW_F2   16777216
#define OW_FAST 25165824
__device__ __nv_bfloat16 g_wb_hi[NW_TOTAL];
__device__ __nv_bfloat16 g_wb_lo[NW_TOTAL];
__device__ __nv_bfloat16 g_actA_hi[MROWS * 1024];   // narrow activations (x/t/attn-out/ln)
__device__ __nv_bfloat16 g_actA_lo[MROWS * 1024];
__device__ __nv_bfloat16 g_actB_hi[MROWS * 4096];   // qkv (3072) / ffn hidden (4096)
__device__ __nv_bfloat16 g_actB_lo[MROWS * 4096];

__device__ __forceinline__ float gelu_exact(float v) {
    return 0.5f * v * (1.0f + erff(v * 0.7071067811865476f));
}
__device__ __forceinline__ uint32_t pack_bf16(float a, float b) {
    __nv_bfloat162 t = __floats2bfloat162_rn(a, b);
    return *(uint32_t*)&t;
}

// =================== portable tensor-core primitives (sm_80+ PTX) ============
__device__ __forceinline__ uint32_t smem_u32(const void* p) {
    uint32_t a;
    asm("{ .reg .u64 t; cvta.to.shared.u64 t, %1; cvt.u32.u64 %0, t; }" : "=r"(a) : "l"(p));
    return a;
}
__device__ __forceinline__ void ldm_x4(uint32_t& r0, uint32_t& r1, uint32_t& r2, uint32_t& r3,
                                       uint32_t addr) {
    asm volatile("ldmatrix.sync.aligned.m8n8.x4.shared.b16 {%0,%1,%2,%3}, [%4];"
                 : "=r"(r0), "=r"(r1), "=r"(r2), "=r"(r3) : "r"(addr));
}
__device__ __forceinline__ void ldm_x4_t(uint32_t& r0, uint32_t& r1, uint32_t& r2, uint32_t& r3,
                                         uint32_t addr) {
    asm volatile("ldmatrix.sync.aligned.m8n8.x4.trans.shared.b16 {%0,%1,%2,%3}, [%4];"
                 : "=r"(r0), "=r"(r1), "=r"(r2), "=r"(r3) : "r"(addr));
}
__device__ __forceinline__ void mma16816(float* c, uint32_t a0, uint32_t a1, uint32_t a2,
                                         uint32_t a3, uint32_t b0, uint32_t b1) {
    asm volatile(
        "mma.sync.aligned.m16n8k16.row.col.f32.bf16.bf16.f32 "
        "{%0,%1,%2,%3}, {%4,%5,%6,%7}, {%8,%9}, {%0,%1,%2,%3};"
        : "+f"(c[0]), "+f"(c[1]), "+f"(c[2]), "+f"(c[3])
        : "r"(a0), "r"(a1), "r"(a2), "r"(a3), "r"(b0), "r"(b1));
}
__device__ __forceinline__ void cp16(uint32_t saddr, const void* g) {
    asm volatile("cp.async.cg.shared.global [%0], [%1], 16;" :: "r"(saddr), "l"(g));
}
#define CP_COMMIT() asm volatile("cp.async.commit_group;" ::: "memory")
#define CP_WAIT(N)  asm volatile("cp.async.wait_group %0;" :: "n"(N) : "memory")

// =================== mma.sync GEMM: C[M,N] = A[M,K] @ B[N,K]^T ===============
// 128x128 block, 8 warps (2M x 4N), warp tile 64x32, K-chunk 32,
// 3 mma per fragment (hh + hl + lh). smem rows 80B: conflict-free ldmatrix.
// EPI: 0 = fp32, 1 = gelu fp32, 2 = bf16 hi/lo split, 3 = gelu + split
#define TIL   10240
#define STAGE (4 * TIL)
#define SMT   (2 * STAGE)

__device__ __forceinline__ void copy_tile_async(uint32_t sdst, const __nv_bfloat16* __restrict__ g,
                                                int row0, int K, int k0, int tid) {
    #pragma unroll
    for (int i = 0; i < 2; i++) {
        int idx = tid + i * 256;
        int r = idx >> 2, c4 = idx & 3;
        cp16(sdst + r * 80 + c4 * 16, g + (size_t)(row0 + r) * K + k0 + c4 * 8);
    }
}

template<int EPI>
__global__ __launch_bounds__(256) void mma_gemm(
        const __nv_bfloat16* __restrict__ Ahi, const __nv_bfloat16* __restrict__ Alo,
        const __nv_bfloat16* __restrict__ Bhi, const __nv_bfloat16* __restrict__ Blo,
        float* __restrict__ C, __nv_bfloat16* __restrict__ Chi,
        __nv_bfloat16* __restrict__ Clo, int N, int K) {
    extern __shared__ __align__(128) char smem[];
    uint32_t sb = smem_u32(smem);
    int tid = threadIdx.x, lane = tid & 31, warp = tid >> 5;
    int wm = warp & 1, wn = warp >> 1;
    int rowB = blockIdx.y * 128, colB = blockIdx.x * 128;

    int aRow = wm * 64 + (lane & 15);
    int aK   = (lane >> 4) * 8;
    uint32_t aOff = (uint32_t)(aRow * 80 + aK * 2);
    int bRow = wn * 32 + ((lane >> 4) << 3) + (lane & 7);
    int bK   = ((lane >> 3) & 1) * 8;
    uint32_t bOff = (uint32_t)(bRow * 80 + bK * 2);

    float acc[4][4][4];
    #pragma unroll
    for (int i = 0; i < 4; i++)
        #pragma unroll
        for (int j = 0; j < 4; j++)
            #pragma unroll
            for (int k = 0; k < 4; k++) acc[i][j][k] = 0.0f;

    int nch = K >> 5;
    {
        copy_tile_async(sb + 0 * TIL, Ahi, rowB, K, 0, tid);
        copy_tile_async(sb + 1 * TIL, Alo, rowB, K, 0, tid);
        copy_tile_async(sb + 2 * TIL, Bhi, colB, K, 0, tid);
        copy_tile_async(sb + 3 * TIL, Blo, colB, K, 0, tid);
        CP_COMMIT();
    }

    for (int c = 0; c < nch; c++) {
        if (c + 1 < nch) {
            uint32_t sn = sb + ((c + 1) & 1) * STAGE;
            int k0 = (c + 1) * 32;
            copy_tile_async(sn + 0 * TIL, Ahi, rowB, K, k0, tid);
            copy_tile_async(sn + 1 * TIL, Alo, rowB, K, k0, tid);
            copy_tile_async(sn + 2 * TIL, Bhi, colB, K, k0, tid);
            copy_tile_async(sn + 3 * TIL, Blo, colB, K, k0, tid);
            CP_COMMIT();
            CP_WAIT(1);
        } else {
            CP_WAIT(0);
        }
        __syncthreads();

        uint32_t ss = sb + (c & 1) * STAGE;
        uint32_t sAh = ss + aOff, sAl = ss + TIL + aOff;
        uint32_t sBh = ss + 2 * TIL + bOff, sBl = ss + 3 * TIL + bOff;

        #pragma unroll
        for (int k16 = 0; k16 < 2; k16++) {
            uint32_t kb = k16 * 32;
            uint32_t ah[4][4], al[4][4], bh[2][4], bl[2][4];
            #pragma unroll
            for (int mt = 0; mt < 4; mt++) {
                uint32_t off = (uint32_t)(mt * 16 * 80) + kb;
                ldm_x4(ah[mt][0], ah[mt][1], ah[mt][2], ah[mt][3], sAh + off);
                ldm_x4(al[mt][0], al[mt][1], al[mt][2], al[mt][3], sAl + off);
            }
            #pragma unroll
            for (int nh = 0; nh < 2; nh++) {
                uint32_t off = (uint32_t)(nh * 16 * 80) + kb;
                ldm_x4(bh[nh][0], bh[nh][1], bh[nh][2], bh[nh][3], sBh + off);
                ldm_x4(bl[nh][0], bl[nh][1], bl[nh][2], bl[nh][3], sBl + off);
            }
            #pragma unroll
            for (int mt = 0; mt < 4; mt++)
                #pragma unroll
                for (int nt = 0; nt < 4; nt++) {
                    int nh = nt >> 1, o = (nt & 1) * 2;
                    mma16816(acc[mt][nt], ah[mt][0], ah[mt][1], ah[mt][2], ah[mt][3],
                             bh[nh][o], bh[nh][o + 1]);
                    mma16816(acc[mt][nt], ah[mt][0], ah[mt][1], ah[mt][2], ah[mt][3],
                             bl[nh][o], bl[nh][o + 1]);
                    mma16816(acc[mt][nt], al[mt][0], al[mt][1], al[mt][2], al[mt][3],
                             bh[nh][o], bh[nh][o + 1]);
                }
        }
        __syncthreads();
    }

    int r = lane >> 2, c2 = (lane & 3) * 2;
    int row0 = rowB + wm * 64, col0 = colB + wn * 32;
    #pragma unroll
    for (int mt = 0; mt < 4; mt++)
        #pragma unroll
        for (int nt = 0; nt < 4; nt++) {
            float v0 = acc[mt][nt][0], v1 = acc[mt][nt][1];
            float v2 = acc[mt][nt][2], v3 = acc[mt][nt][3];
            if (EPI == 1 || EPI == 3) {
                v0 = gelu_exact(v0); v1 = gelu_exact(v1);
                v2 = gelu_exact(v2); v3 = gelu_exact(v3);
            }
            int row = row0 + mt * 16 + r, col = col0 + nt * 8 + c2;
            if (EPI <= 1) {
                float2 p0 = {v0, v1}, p1 = {v2, v3};
                *(float2*)(C + (size_t)row * N + col) = p0;
                *(float2*)(C + (size_t)(row + 8) * N + col) = p1;
            } else {
                __nv_bfloat16 h0 = __float2bfloat16(v0), h1 = __float2bfloat16(v1);
                __nv_bfloat16 h2 = __float2bfloat16(v2), h3 = __float2bfloat16(v3);
                float r0 = v0 - __bfloat162float(h0), r1 = v1 - __bfloat162float(h1);
                float r2 = v2 - __bfloat162float(h2), r3 = v3 - __bfloat162float(h3);
                uint32_t hp0 = (uint32_t)__bfloat16_as_ushort(h0) |
                               ((uint32_t)__bfloat16_as_ushort(h1) << 16);
                uint32_t hp1 = (uint32_t)__bfloat16_as_ushort(h2) |
                               ((uint32_t)__bfloat16_as_ushort(h3) << 16);
                *(uint32_t*)(Chi + (size_t)row * N + col) = hp0;
                *(uint32_t*)(Chi + (size_t)(row + 8) * N + col) = hp1;
                *(uint32_t*)(Clo + (size_t)row * N + col) = pack_bf16(r0, r1);
                *(uint32_t*)(Clo + (size_t)(row + 8) * N + col) = pack_bf16(r2, r3);
            }
        }
}

// =================== tensor-core flash attention =============================
// qkv hi/lo [MROWS, 3072] -> out split hi/lo [MROWS, 1024].
// grid (S/128, H, B), 256 threads; warp = 16 q rows; KV tiles of 64.
#define ATT_SQH 0
#define ATT_SQL 18432
#define ATT_SKH 36864
#define ATT_SKL 46080
#define ATT_SVH 55296
#define ATT_SVL 64512
#define ATT_SMEM 73728
#define QSTR 3072

__global__ __launch_bounds__(256) void attn_mma(
        const __nv_bfloat16* __restrict__ qh, const __nv_bfloat16* __restrict__ ql,
        __nv_bfloat16* __restrict__ oh, __nv_bfloat16* __restrict__ ol) {
    extern __shared__ __align__(128) char smem[];
    uint32_t sb = smem_u32(smem);
    int tid = threadIdx.x, lane = tid & 31, warp = tid >> 5;
    int qt = blockIdx.x, h = blockIdx.y, b = blockIdx.z;
    int rb = b * SS;

    // load Q tile (hi + lo)
    #pragma unroll
    for (int i = 0; i < 4; i++) {
        int idx = tid + i * 256;
        int r = idx >> 3, c8 = idx & 7;
        size_t srow = (size_t)(rb + qt * 128 + r) * QSTR + h * 64 + c8 * 8;
        *(uint4*)(smem + ATT_SQH + r * 144 + c8 * 16) = *(const uint4*)(qh + srow);
        *(uint4*)(smem + ATT_SQL + r * 144 + c8 * 16) = *(const uint4*)(ql + srow);
    }

    float m0 = -1e30f, m1 = -1e30f, l0 = 0.0f, l1 = 0.0f;
    float accO[8][4];
    #pragma unroll
    for (int i = 0; i < 8; i++)
        #pragma unroll
        for (int j = 0; j < 4; j++) accO[i][j] = 0.0f;

    uint32_t aAddr = sb + ATT_SQH + (uint32_t)((warp * 16 + (lane & 15)) * 144 + (lane >> 4) * 16);
    uint32_t bOff  = (uint32_t)(((lane & 7) + ((lane >> 4) << 3)) * 144 + ((lane >> 3) & 1) * 16);
    uint32_t vOff  = (uint32_t)(((lane & 7) + ((lane >> 3) & 1) * 8) * 144 + ((lane >> 4) & 1) * 16);

    __syncthreads();

    for (int kv0 = 0; kv0 < SS; kv0 += 64) {
        // load K,V tiles (hi + lo)
        #pragma unroll
        for (int i = 0; i < 2; i++) {
            int idx = tid + i * 256;
            int r = idx >> 3, c8 = idx & 7;
            size_t srow = (size_t)(rb + kv0 + r) * QSTR + h * 64 + c8 * 8;
            *(uint4*)(smem + ATT_SKH + r * 144 + c8 * 16) = *(const uint4*)(qh + srow + 1024);
            *(uint4*)(smem + ATT_SKL + r * 144 + c8 * 16) = *(const uint4*)(ql + srow + 1024);
            *(uint4*)(smem + ATT_SVH + r * 144 + c8 * 16) = *(const uint4*)(qh + srow + 2048);
            *(uint4*)(smem + ATT_SVL + r * 144 + c8 * 16) = *(const uint4*)(ql + srow + 2048);
        }
        __syncthreads();

        // scores S = Q @ K^T (3-term split)
        float s[8][4];
        #pragma unroll
        for (int i = 0; i < 8; i++)
            #pragma unroll
            for (int j = 0; j < 4; j++) s[i][j] = 0.0f;

        #pragma unroll
        for (int kc = 0; kc < 4; kc++) {
            uint32_t ah0, ah1, ah2, ah3, al0, al1, al2, al3;
            ldm_x4(ah0, ah1, ah2, ah3, aAddr + kc * 32);
            ldm_x4(al0, al1, al2, al3, aAddr + (ATT_SQL - ATT_SQH) + kc * 32);
            #pragma unroll
            for (int nh = 0; nh < 4; nh++) {
                uint32_t ba = sb + ATT_SKH + (uint32_t)(nh * 16 * 144) + bOff + kc * 32;
                uint32_t bh_[4], bl_[4];
                ldm_x4(bh_[0], bh_[1], bh_[2], bh_[3], ba);
                ldm_x4(bl_[0], bl_[1], bl_[2], bl_[3], ba + (ATT_SKL - ATT_SKH));
                #pragma unroll
                for (int o = 0; o < 2; o++) {
                    int nt = nh * 2 + o;
                    mma16816(s[nt], ah0, ah1, ah2, ah3, bh_[o * 2], bh_[o * 2 + 1]);
                    mma16816(s[nt], ah0, ah1, ah2, ah3, bl_[o * 2], bl_[o * 2 + 1]);
                    mma16816(s[nt], al0, al1, al2, al3, bh_[o * 2], bh_[o * 2 + 1]);
                }
            }
        }

        // scale + online softmax
        float mx0 = -1e30f, mx1 = -1e30f;
        #pragma unroll
        for (int nt = 0; nt < 8; nt++) {
            s[nt][0] *= 0.125f; s[nt][1] *= 0.125f; s[nt][2] *= 0.125f; s[nt][3] *= 0.125f;
            mx0 = fmaxf(mx0, fmaxf(s[nt][0], s[nt][1]));
            mx1 = fmaxf(mx1, fmaxf(s[nt][2], s[nt][3]));
        }
        mx0 = fmaxf(mx0, __shfl_xor_sync(0xffffffffu, mx0, 1));
        mx0 = fmaxf(mx0, __shfl_xor_sync(0xffffffffu, mx0, 2));
        mx1 = fmaxf(mx1, __shfl_xor_sync(0xffffffffu, mx1, 1));
        mx1 = fmaxf(mx1, __shfl_xor_sync(0xffffffffu, mx1, 2));
        float mn0 = fmaxf(m0, mx0), mn1 = fmaxf(m1, mx1);
        float alpha0 = __expf(m0 - mn0), alpha1 = __expf(m1 - mn1);
        m0 = mn0; m1 = mn1;
        float sum0 = 0.0f, sum1 = 0.0f;
        #pragma unroll
        for (int nt = 0; nt < 8; nt++) {
            s[nt][0] = __expf(s[nt][0] - m0);
            s[nt][1] = __expf(s[nt][1] - m0);
            s[nt][2] = __expf(s[nt][2] - m1);
            s[nt][3] = __expf(s[nt][3] - m1);
            sum0 += s[nt][0] + s[nt][1];
            sum1 += s[nt][2] + s[nt][3];
        }
        sum0 += __shfl_xor_sync(0xffffffffu, sum0, 1);
        sum0 += __shfl_xor_sync(0xffffffffu, sum0, 2);
        sum1 += __shfl_xor_sync(0xffffffffu, sum1, 1);
        sum1 += __shfl_xor_sync(0xffffffffu, sum1, 2);
        l0 = l0 * alpha0 + sum0;
        l1 = l1 * alpha1 + sum1;
        #pragma unroll
        for (int dt = 0; dt < 8; dt++) {
            accO[dt][0] *= alpha0; accO[dt][1] *= alpha0;
            accO[dt][2] *= alpha1; accO[dt][3] *= alpha1;
        }

        // O += P @ V (P split in registers; V via trans ldmatrix)
        #pragma unroll
        for (int kc2 = 0; kc2 < 4; kc2++) {
            int n0 = kc2 * 2, n1 = kc2 * 2 + 1;
            __nv_bfloat16 h00 = __float2bfloat16(s[n0][0]), h01 = __float2bfloat16(s[n0][1]);
            __nv_bfloat16 h02 = __float2bfloat16(s[n0][2]), h03 = __float2bfloat16(s[n0][3]);
            __nv_bfloat16 h10 = __float2bfloat16(s[n1][0]), h11 = __float2bfloat16(s[n1][1]);
            __nv_bfloat16 h12 = __float2bfloat16(s[n1][2]), h13 = __float2bfloat16(s[n1][3]);
            uint32_t ph0 = (uint32_t)__bfloat16_as_ushort(h00) | ((uint32_t)__bfloat16_as_ushort(h01) << 16);
            uint32_t ph1 = (uint32_t)__bfloat16_as_ushort(h02) | ((uint32_t)__bfloat16_as_ushort(h03) << 16);
            uint32_t ph2 = (uint32_t)__bfloat16_as_ushort(h10) | ((uint32_t)__bfloat16_as_ushort(h11) << 16);
            uint32_t ph3 = (uint32_t)__bfloat16_as_ushort(h12) | ((uint32_t)__bfloat16_as_ushort(h13) << 16);
            uint32_t pl0 = pack_bf16(s[n0][0] - __bfloat162float(h00), s[n0][1] - __bfloat162float(h01));
            uint32_t pl1 = pack_bf16(s[n0][2] - __bfloat162float(h02), s[n0][3] - __bfloat162float(h03));
            uint32_t pl2 = pack_bf16(s[n1][0] - __bfloat162float(h10), s[n1][1] - __bfloat162float(h11));
            uint32_t pl3 = pack_bf16(s[n1][2] - __bfloat162float(h12), s[n1][3] - __bfloat162float(h13));
            #pragma unroll
            for (int nd = 0; nd < 4; nd++) {
                uint32_t va = sb + ATT_SVH + (uint32_t)(kc2 * 16 * 144) + vOff + nd * 32;
                uint32_t vh_[4], vl_[4];
                ldm_x4_t(vh_[0], vh_[1], vh_[2], vh_[3], va);
                ldm_x4_t(vl_[0], vl_[1], vl_[2], vl_[3], va + (ATT_SVL - ATT_SVH));
                #pragma unroll
                for (int o = 0; o < 2; o++) {
                    int dt = nd * 2 + o;
                    mma16816(accO[dt], ph0, ph1, ph2, ph3, vh_[o * 2], vh_[o * 2 + 1]);
                    mma16816(accO[dt], ph0, ph1, ph2, ph3, vl_[o * 2], vl_[o * 2 + 1]);
                    mma16816(accO[dt], pl0, pl1, pl2, pl3, vh_[o * 2], vh_[o * 2 + 1]);
                }
            }
        }
        __syncthreads();
    }

    // epilogue: normalize, split to bf16 hi/lo, store
    float inv0 = 1.0f / l0, inv1 = 1.0f / l1;
    int g = lane >> 2, c2 = (lane & 3) * 2;
    int row = rb + qt * 128 + warp * 16 + g;
    int colb = h * 64 + c2;
    #pragma unroll
    for (int dt = 0; dt < 8; dt++) {
        float v0 = accO[dt][0] * inv0, v1 = accO[dt][1] * inv0;
        float v2 = accO[dt][2] * inv1, v3 = accO[dt][3] * inv1;
        __nv_bfloat16 h0 = __float2bfloat16(v0), h1 = __float2bfloat16(v1);
        __nv_bfloat16 h2 = __float2bfloat16(v2), h3 = __float2bfloat16(v3);
        uint32_t hp0 = (uint32_t)__bfloat16_as_ushort(h0) | ((uint32_t)__bfloat16_as_ushort(h1) << 16);
        uint32_t hp1 = (uint32_t)__bfloat16_as_ushort(h2) | ((uint32_t)__bfloat16_as_ushort(h3) << 16);
        int col = colb + dt * 8;
        *(uint32_t*)(oh + (size_t)row * EE + col) = hp0;
        *(uint32_t*)(oh + (size_t)(row + 8) * EE + col) = hp1;
        *(uint32_t*)(ol + (size_t)row * EE + col) =
            pack_bf16(v0 - __bfloat162float(h0), v1 - __bfloat162float(h1));
        *(uint32_t*)(ol + (size_t)(row + 8) * EE + col) =
            pack_bf16(v2 - __bfloat162float(h2), v3 - __bfloat162float(h3));
    }
}

// ---------------- fp32 -> bf16 hi/lo split -----------------------------------
__global__ __launch_bounds__(256) void split_kernel(const float* __restrict__ in,
                                                    __nv_bfloat16* __restrict__ hi,
                                                    __nv_bfloat16* __restrict__ lo,
                                                    int n4) {
    int i = blockIdx.x * 256 + threadIdx.x;
    if (i >= n4) return;
    float4 v = ((const float4*)in)[i];
    float x[4] = {v.x, v.y, v.z, v.w};
    uint32_t hw[4], lw[4];
    #pragma unroll
    for (int k = 0; k < 4; k++) {
        __nv_bfloat16 h = __float2bfloat16(x[k]);
        float rr = x[k] - __bfloat162float(h);
        __nv_bfloat16 l = __float2bfloat16(rr);
        hw[k] = (uint32_t)__bfloat16_as_ushort(h);
        lw[k] = (uint32_t)__bfloat16_as_ushort(l);
    }
    uint2 ho, loo;
    ho.x  = hw[0] | (hw[1] << 16);  ho.y  = hw[2] | (hw[3] << 16);
    loo.x = lw[0] | (lw[1] << 16);  loo.y = lw[2] | (lw[3] << 16);
    ((uint2*)hi)[i] = ho;
    ((uint2*)lo)[i] = loo;
}

// ---------------- y = LN(a + b) * g + beta (+ bf16 split) --------------------
__global__ __launch_bounds__(256) void add_ln_split_kernel(const float* __restrict__ a,
                                                           const float* __restrict__ bsrc,
                                                           const float* __restrict__ g,
                                                           const float* __restrict__ beta,
                                                           float* __restrict__ y,
                                                           __nv_bfloat16* __restrict__ yh,
                                                           __nv_bfloat16* __restrict__ yl) {
    int row = blockIdx.x;
    int tid = threadIdx.x;
    const float* ar = a + (size_t)row * EE;
    const float* br = bsrc + (size_t)row * EE;
    float v[4];
    float s = 0.0f, s2 = 0.0f;
    #pragma unroll
    for (int k = 0; k < 4; k++) {
        float t = ar[tid + 256 * k] + br[tid + 256 * k];
        v[k] = t; s += t; s2 += t * t;
    }
    __shared__ float red[18];
    #pragma unroll
    for (int off = 16; off; off >>= 1) {
        s  += __shfl_xor_sync(0xffffffffu, s,  off);
        s2 += __shfl_xor_sync(0xffffffffu, s2, off);
    }
    int wid = tid >> 5, lid = tid & 31;
    if (lid == 0) { red[wid] = s; red[wid + 8] = s2; }
    __syncthreads();
    if (tid < 32) {
        float a1 = (tid < 8) ? red[tid] : 0.0f;
        float a2 = (tid < 8) ? red[tid + 8] : 0.0f;
        #pragma unroll
        for (int off = 4; off; off >>= 1) {
            a1 += __shfl_xor_sync(0xffffffffu, a1, off);
            a2 += __shfl_xor_sync(0xffffffffu, a2, off);
        }
        if (tid == 0) { red[16] = a1; red[17] = a2; }
    }
    __syncthreads();
    float mu = red[16] * (1.0f / EE);
    float var = red[17] * (1.0f / EE) - mu * mu;
    float rs = rsqrtf(var + 1e-5f);
    float* yr = y + (size_t)row * EE;
    __nv_bfloat16* yhr = yh + (size_t)row * EE;
    __nv_bfloat16* ylr = yl + (size_t)row * EE;
    #pragma unroll
    for (int k = 0; k < 4; k++) {
        int c = tid + 256 * k;
        float val = (v[k] - mu) * rs * g[c] + beta[c];
        yr[c] = val;
        __nv_bfloat16 h = __float2bfloat16(val);
        yhr[c] = h;
        ylr[c] = __float2bfloat16(val - __bfloat162float(h));
    }
}

// ---------------- mean-pool over S -------------------------------------------
__global__ __launch_bounds__(256) void pool_kernel(const float* __restrict__ x,
                                                   float* __restrict__ pooled) {
    int idx = blockIdx.x * 256 + threadIdx.x;
    int b = idx >> 10, e = idx & 1023;
    const float* p = x + (size_t)b * SS * EE + e;
    float s = 0.0f;
    for (int sI = 0; sI < SS; sI++) s += p[(size_t)sI * EE];
    pooled[idx] = s * (1.0f / SS);
}

// ---------------- complexity estimator ---------------------------------------
__global__ __launch_bounds__(256) void ce_kernel(const float* __restrict__ pooled,
                                                 const float* __restrict__ w1,
                                                 const float* __restrict__ b1,
                                                 const float* __restrict__ w2,
                                                 const float* __restrict__ b2,
                                                 float* __restrict__ out) {
    int b = blockIdx.x, j = threadIdx.x;
    const float* p = pooled + b * EE;
    const float* w = w1 + (size_t)j * EE;
    float s = b1[j];
    for (int k = 0; k < EE; k++) s = fmaf(p[k], w[k], s);
    float h = fmaxf(s, 0.0f);
    __shared__ float red[256];
    red[j] = h * w2[j];
    __syncthreads();
    for (int off = 128; off; off >>= 1) {
        if (j < off) red[j] += red[j + off];
        __syncthreads();
    }
    if (j == 0) {
        float logit = red[0] + b2[0];
        float prob = 1.0f / (1.0f + expf(-logit));
        out[OFF_PROBS + b] = prob;
        out[OFF_MODE + b] = (prob > 0.5f) ? 1.0f : 0.0f;
    }
}

// ---------------- select + mean(mode) ----------------------------------------
__global__ __launch_bounds__(256) void finalize_kernel(const float* __restrict__ t,
                                                       const float* __restrict__ f,
                                                       float* __restrict__ out) {
    size_t i = (size_t)blockIdx.x * 256 + threadIdx.x;
    int b = (int)((i * 4) >> 20);
    float m = out[OFF_MODE + b];
    float4 r = (m > 0.5f) ? ((const float4*)t)[i] : ((const float4*)f)[i];
    ((float4*)out)[i] = r;
    if (i == 0) {
        float sAcc = 0.0f;
        for (int k = 0; k < 8; k++) sAcc += out[OFF_MODE + k];
        out[OFF_MEAN] = sAcc * 0.125f;
    }
}

// -----------------------------------------------------------------------------
extern "C" void kernel_launch(void* const* d_in, const int* in_sizes, int n_in,
                              void* d_out, int out_size) {
    const float* x      = (const float*)d_in[0];
    const float* w_in   = (const float*)d_in[1];
    const float* w_out  = (const float*)d_in[2];
    const float* ffn_w1 = (const float*)d_in[3];
    const float* ffn_w2 = (const float*)d_in[4];
    const float* ln1_g  = (const float*)d_in[5];
    const float* ln1_b  = (const float*)d_in[6];
    const float* ln2_g  = (const float*)d_in[7];
    const float* ln2_b  = (const float*)d_in[8];
    const float* ce_w1  = (const float*)d_in[9];
    const float* ce_b1  = (const float*)d_in[10];
    const float* ce_w2  = (const float*)d_in[11];
    const float* ce_b2  = (const float*)d_in[12];
    const float* fast_w = (const float*)d_in[13];
    float* out = (float*)d_out;

    float *bufA, *bufB, *bufT, *bufT1, *bufFast, *pooled;
    __nv_bfloat16 *wbh, *wbl, *ah, *al, *bh, *bl;
    cudaGetSymbolAddress((void**)&bufA, g_bufA);
    cudaGetSymbolAddress((void**)&bufB, g_bufB);
    cudaGetSymbolAddress((void**)&bufT, g_bufT);
    cudaGetSymbolAddress((void**)&bufT1, g_bufT1);
    cudaGetSymbolAddress((void**)&bufFast, g_bufFast);
    cudaGetSymbolAddress((void**)&pooled, g_pooled);
    cudaGetSymbolAddress((void**)&wbh, g_wb_hi);
    cudaGetSymbolAddress((void**)&wbl, g_wb_lo);
    cudaGetSymbolAddress((void**)&ah, g_actA_hi);
    cudaGetSymbolAddress((void**)&al, g_actA_lo);
    cudaGetSymbolAddress((void**)&bh, g_actB_hi);
    cudaGetSymbolAddress((void**)&bl, g_actB_lo);

    cudaFuncSetAttribute(mma_gemm<0>, cudaFuncAttributeMaxDynamicSharedMemorySize, SMT);
    cudaFuncSetAttribute(mma_gemm<1>, cudaFuncAttributeMaxDynamicSharedMemorySize, SMT);
    cudaFuncSetAttribute(mma_gemm<2>, cudaFuncAttributeMaxDynamicSharedMemorySize, SMT);
    cudaFuncSetAttribute(mma_gemm<3>, cudaFuncAttributeMaxDynamicSharedMemorySize, SMT);
    cudaFuncSetAttribute(attn_mma, cudaFuncAttributeMaxDynamicSharedMemorySize, ATT_SMEM);

    // weight splits
    split_kernel<<<(2*3*EE*EE/4)/256, 256>>>(w_in,   wbh + OW_IN,   wbl + OW_IN,   2*3*EE*EE/4);
    split_kernel<<<(2*EE*EE/4)/256,   256>>>(w_out,  wbh + OW_OUT,  wbl + OW_OUT,  2*EE*EE/4);
    split_kernel<<<(2*4*EE*EE/4)/256, 256>>>(ffn_w1, wbh + OW_F1,   wbl + OW_F1,   2*4*EE*EE/4);
    split_kernel<<<(2*4*EE*EE/4)/256, 256>>>(ffn_w2, wbh + OW_F2,   wbl + OW_F2,   2*4*EE*EE/4);
    split_kernel<<<(EE*EE/4)/256,     256>>>(fast_w, wbh + OW_FAST, wbl + OW_FAST, EE*EE/4);

    // complexity estimator
    pool_kernel<<<(BB * EE) / 256, 256>>>(x, pooled);
    ce_kernel<<<BB, 256>>>(pooled, ce_w1, ce_b1, ce_w2, ce_b2, out);

    // split x -> A (serves fast path + layer-0 qkv)
    split_kernel<<<(MROWS*EE/4)/256, 256>>>(x, ah, al, MROWS*EE/4);

    // fast path: gelu(x @ fast_w^T) -> fp32
    mma_gemm<1><<<dim3(EE/128, MROWS/128), 256, SMT>>>(
        ah, al, wbh + OW_FAST, wbl + OW_FAST, bufFast, nullptr, nullptr, EE, EE);

    // thinking path
    const float* tin = x;
    for (int l = 0; l < LL; l++) {
        // qkv: A -> B (bf16 split out)
        mma_gemm<2><<<dim3(3*EE/128, MROWS/128), 256, SMT>>>(
            ah, al, wbh + OW_IN + (size_t)l*3*EE*EE, wbl + OW_IN + (size_t)l*3*EE*EE,
            nullptr, bh, bl, 3*EE, EE);
        // attention: B -> A (bf16 split out)
        attn_mma<<<dim3(SS/128, HH, BB), 256, ATT_SMEM>>>(bh, bl, ah, al);
        // out-proj: A -> bufA fp32
        mma_gemm<0><<<dim3(EE/128, MROWS/128), 256, SMT>>>(
            ah, al, wbh + OW_OUT + (size_t)l*EE*EE, wbl + OW_OUT + (size_t)l*EE*EE,
            bufA, nullptr, nullptr, EE, EE);
        // LN1: tin + bufA -> bufT1 fp32 + A split
        add_ln_split_kernel<<<MROWS, 256>>>(tin, bufA, ln1_g + l*EE, ln1_b + l*EE,
                                            bufT1, ah, al);
        // ffn1 + gelu: A -> B split (4096-wide)
        mma_gemm<3><<<dim3(4*EE/128, MROWS/128), 256, SMT>>>(
            ah, al, wbh + OW_F1 + (size_t)l*4*EE*EE, wbl + OW_F1 + (size_t)l*4*EE*EE,
            nullptr, bh, bl, 4*EE, EE);
        // ffn2: B -> bufB fp32
        mma_gemm<0><<<dim3(EE/128, MROWS/128), 256, SMT>>>(
            bh, bl, wbh + OW_F2 + (size_t)l*4*EE*EE, wbl + OW_F2 + (size_t)l*4*EE*EE,
            bufB, nullptr, nullptr, EE, 4*EE);
        // LN2: bufT1 + bufB -> bufT fp32 + A split (next layer input)
        add_ln_split_kernel<<<MROWS, 256>>>(bufT1, bufB, ln2_g + l*EE, ln2_b + l*EE,
                                            bufT, ah, al);
        tin = bufT;
    }

    // out = where(mode, t, fast); also mean(mode)
    finalize_kernel<<<(MROWS * EE / 4) / 256, 256>>>(bufT, bufFast, out);
}

// round 6
// speedup vs baseline: 2.9577x; 1.1172x over previous
#include <cuda_runtime.h>
#include <cuda_bf16.h>
#include <math.h>
#include <stdint.h>

#define BB 8
#define SS 1024
#define EE 1024
#define HH 16
#define DD 64
#define LL 2
#define MROWS (BB*SS)              // 8192
#define OUT_MAIN (BB*SS*EE)        // 8388608
#define OFF_PROBS OUT_MAIN
#define OFF_MODE  (OUT_MAIN + 8)
#define OFF_MEAN  (OUT_MAIN + 16)

// ---------------- scratch (device globals; no allocation allowed) ------------
__device__ float g_bufA[MROWS * EE];     // out-proj fp32
__device__ float g_bufB[MROWS * EE];     // ffn2 out fp32
__device__ float g_bufT[MROWS * EE];     // t (post layer)
__device__ float g_bufT1[MROWS * EE];    // t1 (post LN1)
__device__ float g_bufFast[MROWS * EE];  // fast path
__device__ float g_pooled[BB * EE];

// bf16 split buffers
#define NW_TOTAL 26214400
#define OW_IN   0
#define OW_OUT  6291456
#define OW_F1   8388608
#define OW_F2   16777216
#define OW_FAST 25165824
__device__ __nv_bfloat16 g_wb_hi[NW_TOTAL];
__device__ __nv_bfloat16 g_wb_lo[NW_TOTAL];
__device__ __nv_bfloat16 g_actA_hi[MROWS * 1024];   // narrow activations
__device__ __nv_bfloat16 g_actA_lo[MROWS * 1024];
__device__ __nv_bfloat16 g_actB_hi[MROWS * 4096];   // qkv (3072) / ffn hidden (4096)
__device__ __nv_bfloat16 g_actB_lo[MROWS * 4096];

__device__ __forceinline__ float gelu_exact(float v) {
    return 0.5f * v * (1.0f + erff(v * 0.7071067811865476f));
}
__device__ __forceinline__ uint32_t pack_bf16(float a, float b) {
    __nv_bfloat162 t = __floats2bfloat162_rn(a, b);
    return *(uint32_t*)&t;
}

// =================== portable tensor-core primitives (sm_80+ PTX) ============
__device__ __forceinline__ uint32_t smem_u32(const void* p) {
    uint32_t a;
    asm("{ .reg .u64 t; cvta.to.shared.u64 t, %1; cvt.u32.u64 %0, t; }" : "=r"(a) : "l"(p));
    return a;
}
__device__ __forceinline__ void ldm_x4(uint32_t& r0, uint32_t& r1, uint32_t& r2, uint32_t& r3,
                                       uint32_t addr) {
    asm volatile("ldmatrix.sync.aligned.m8n8.x4.shared.b16 {%0,%1,%2,%3}, [%4];"
                 : "=r"(r0), "=r"(r1), "=r"(r2), "=r"(r3) : "r"(addr));
}
__device__ __forceinline__ void ldm_x4_t(uint32_t& r0, uint32_t& r1, uint32_t& r2, uint32_t& r3,
                                         uint32_t addr) {
    asm volatile("ldmatrix.sync.aligned.m8n8.x4.trans.shared.b16 {%0,%1,%2,%3}, [%4];"
                 : "=r"(r0), "=r"(r1), "=r"(r2), "=r"(r3) : "r"(addr));
}
__device__ __forceinline__ void mma16816(float* c, uint32_t a0, uint32_t a1, uint32_t a2,
                                         uint32_t a3, uint32_t b0, uint32_t b1) {
    asm volatile(
        "mma.sync.aligned.m16n8k16.row.col.f32.bf16.bf16.f32 "
        "{%0,%1,%2,%3}, {%4,%5,%6,%7}, {%8,%9}, {%0,%1,%2,%3};"
        : "+f"(c[0]), "+f"(c[1]), "+f"(c[2]), "+f"(c[3])
        : "r"(a0), "r"(a1), "r"(a2), "r"(a3), "r"(b0), "r"(b1));
}
__device__ __forceinline__ void cp16(uint32_t saddr, const void* g) {
    asm volatile("cp.async.cg.shared.global [%0], [%1], 16;" :: "r"(saddr), "l"(g));
}
#define CP_COMMIT() asm volatile("cp.async.commit_group;" ::: "memory")
#define CP_WAIT(N)  asm volatile("cp.async.wait_group %0;" :: "n"(N) : "memory")

// =================== mma.sync GEMM: C[M,N] = A[M,K] @ B[N,K]^T ===============
// 128x128 block, 8 warps (2M x 4N), warp tile 64x32, K-chunk 32,
// 3 mma per fragment. B-frags loaded first, A-frags streamed per mt to cap
// live registers ~120 -> 2 CTAs/SM via __launch_bounds__(256,2).
#define TIL   10240
#define STAGE (4 * TIL)
#define SMT   (2 * STAGE)

__device__ __forceinline__ void copy_tile_async(uint32_t sdst, const __nv_bfloat16* __restrict__ g,
                                                int row0, int K, int k0, int tid) {
    #pragma unroll
    for (int i = 0; i < 2; i++) {
        int idx = tid + i * 256;
        int r = idx >> 2, c4 = idx & 3;
        cp16(sdst + r * 80 + c4 * 16, g + (size_t)(row0 + r) * K + k0 + c4 * 8);
    }
}

template<int EPI>   // 0 fp32, 1 gelu fp32, 2 bf16 split, 3 gelu+split
__global__ __launch_bounds__(256, 2) void mma_gemm(
        const __nv_bfloat16* __restrict__ Ahi, const __nv_bfloat16* __restrict__ Alo,
        const __nv_bfloat16* __restrict__ Bhi, const __nv_bfloat16* __restrict__ Blo,
        float* __restrict__ C, __nv_bfloat16* __restrict__ Chi,
        __nv_bfloat16* __restrict__ Clo, int N, int K) {
    extern __shared__ __align__(128) char smem[];
    uint32_t sb = smem_u32(smem);
    int tid = threadIdx.x, lane = tid & 31, warp = tid >> 5;
    int wm = warp & 1, wn = warp >> 1;
    int rowB = blockIdx.y * 128, colB = blockIdx.x * 128;

    int aRow = wm * 64 + (lane & 15);
    int aK   = (lane >> 4) * 8;
    uint32_t aOff = (uint32_t)(aRow * 80 + aK * 2);
    int bRow = wn * 32 + ((lane >> 4) << 3) + (lane & 7);
    int bK   = ((lane >> 3) & 1) * 8;
    uint32_t bOff = (uint32_t)(bRow * 80 + bK * 2);

    float acc[4][4][4];
    #pragma unroll
    for (int i = 0; i < 4; i++)
        #pragma unroll
        for (int j = 0; j < 4; j++)
            #pragma unroll
            for (int k = 0; k < 4; k++) acc[i][j][k] = 0.0f;

    int nch = K >> 5;
    {
        copy_tile_async(sb + 0 * TIL, Ahi, rowB, K, 0, tid);
        copy_tile_async(sb + 1 * TIL, Alo, rowB, K, 0, tid);
        copy_tile_async(sb + 2 * TIL, Bhi, colB, K, 0, tid);
        copy_tile_async(sb + 3 * TIL, Blo, colB, K, 0, tid);
        CP_COMMIT();
    }

    for (int c = 0; c < nch; c++) {
        if (c + 1 < nch) {
            uint32_t sn = sb + ((c + 1) & 1) * STAGE;
            int k0 = (c + 1) * 32;
            copy_tile_async(sn + 0 * TIL, Ahi, rowB, K, k0, tid);
            copy_tile_async(sn + 1 * TIL, Alo, rowB, K, k0, tid);
            copy_tile_async(sn + 2 * TIL, Bhi, colB, K, k0, tid);
            copy_tile_async(sn + 3 * TIL, Blo, colB, K, k0, tid);
            CP_COMMIT();
            CP_WAIT(1);
        } else {
            CP_WAIT(0);
        }
        __syncthreads();

        uint32_t ss = sb + (c & 1) * STAGE;
        uint32_t sAh = ss + aOff, sAl = ss + TIL + aOff;
        uint32_t sBh = ss + 2 * TIL + bOff, sBl = ss + 3 * TIL + bOff;

        #pragma unroll
        for (int k16 = 0; k16 < 2; k16++) {
            uint32_t kb = k16 * 32;
            // B fragments for this k16 (all 4 nt): 32 regs live
            uint32_t bh[2][4], bl[2][4];
            #pragma unroll
            for (int nh = 0; nh < 2; nh++) {
                uint32_t off = (uint32_t)(nh * 16 * 80) + kb;
                ldm_x4(bh[nh][0], bh[nh][1], bh[nh][2], bh[nh][3], sBh + off);
                ldm_x4(bl[nh][0], bl[nh][1], bl[nh][2], bl[nh][3], sBl + off);
            }
            // stream A fragments per mt: 8 regs live at a time
            #pragma unroll
            for (int mt = 0; mt < 4; mt++) {
                uint32_t off = (uint32_t)(mt * 16 * 80) + kb;
                uint32_t ah0, ah1, ah2, ah3, al0, al1, al2, al3;
                ldm_x4(ah0, ah1, ah2, ah3, sAh + off);
                ldm_x4(al0, al1, al2, al3, sAl + off);
                #pragma unroll
                for (int nt = 0; nt < 4; nt++) {
                    int nh = nt >> 1, o = (nt & 1) * 2;
                    mma16816(acc[mt][nt], ah0, ah1, ah2, ah3, bh[nh][o], bh[nh][o + 1]);
                    mma16816(acc[mt][nt], ah0, ah1, ah2, ah3, bl[nh][o], bl[nh][o + 1]);
                    mma16816(acc[mt][nt], al0, al1, al2, al3, bh[nh][o], bh[nh][o + 1]);
                }
            }
        }
        __syncthreads();
    }

    int r = lane >> 2, c2 = (lane & 3) * 2;
    int row0 = rowB + wm * 64, col0 = colB + wn * 32;
    #pragma unroll
    for (int mt = 0; mt < 4; mt++)
        #pragma unroll
        for (int nt = 0; nt < 4; nt++) {
            float v0 = acc[mt][nt][0], v1 = acc[mt][nt][1];
            float v2 = acc[mt][nt][2], v3 = acc[mt][nt][3];
            if (EPI == 1 || EPI == 3) {
                v0 = gelu_exact(v0); v1 = gelu_exact(v1);
                v2 = gelu_exact(v2); v3 = gelu_exact(v3);
            }
            int row = row0 + mt * 16 + r, col = col0 + nt * 8 + c2;
            if (EPI <= 1) {
                float2 p0 = {v0, v1}, p1 = {v2, v3};
                *(float2*)(C + (size_t)row * N + col) = p0;
                *(float2*)(C + (size_t)(row + 8) * N + col) = p1;
            } else {
                __nv_bfloat16 h0 = __float2bfloat16(v0), h1 = __float2bfloat16(v1);
                __nv_bfloat16 h2 = __float2bfloat16(v2), h3 = __float2bfloat16(v3);
                float r0 = v0 - __bfloat162float(h0), r1 = v1 - __bfloat162float(h1);
                float r2 = v2 - __bfloat162float(h2), r3 = v3 - __bfloat162float(h3);
                uint32_t hp0 = (uint32_t)__bfloat16_as_ushort(h0) |
                               ((uint32_t)__bfloat16_as_ushort(h1) << 16);
                uint32_t hp1 = (uint32_t)__bfloat16_as_ushort(h2) |
                               ((uint32_t)__bfloat16_as_ushort(h3) << 16);
                *(uint32_t*)(Chi + (size_t)row * N + col) = hp0;
                *(uint32_t*)(Chi + (size_t)(row + 8) * N + col) = hp1;
                *(uint32_t*)(Clo + (size_t)row * N + col) = pack_bf16(r0, r1);
                *(uint32_t*)(Clo + (size_t)(row + 8) * N + col) = pack_bf16(r2, r3);
            }
        }
}

// =================== tensor-core flash attention =============================
#define ATT_SQH 0
#define ATT_SQL 18432
#define ATT_SKH 36864
#define ATT_SKL 46080
#define ATT_SVH 55296
#define ATT_SVL 64512
#define ATT_SMEM 73728
#define QSTR 3072

__global__ __launch_bounds__(256) void attn_mma(
        const __nv_bfloat16* __restrict__ qh, const __nv_bfloat16* __restrict__ ql,
        __nv_bfloat16* __restrict__ oh, __nv_bfloat16* __restrict__ ol) {
    extern __shared__ __align__(128) char smem[];
    uint32_t sb = smem_u32(smem);
    int tid = threadIdx.x, lane = tid & 31, warp = tid >> 5;
    int qt = blockIdx.x, h = blockIdx.y, b = blockIdx.z;
    int rb = b * SS;

    #pragma unroll
    for (int i = 0; i < 4; i++) {
        int idx = tid + i * 256;
        int r = idx >> 3, c8 = idx & 7;
        size_t srow = (size_t)(rb + qt * 128 + r) * QSTR + h * 64 + c8 * 8;
        *(uint4*)(smem + ATT_SQH + r * 144 + c8 * 16) = *(const uint4*)(qh + srow);
        *(uint4*)(smem + ATT_SQL + r * 144 + c8 * 16) = *(const uint4*)(ql + srow);
    }

    float m0 = -1e30f, m1 = -1e30f, l0 = 0.0f, l1 = 0.0f;
    float accO[8][4];
    #pragma unroll
    for (int i = 0; i < 8; i++)
        #pragma unroll
        for (int j = 0; j < 4; j++) accO[i][j] = 0.0f;

    uint32_t aAddr = sb + ATT_SQH + (uint32_t)((warp * 16 + (lane & 15)) * 144 + (lane >> 4) * 16);
    uint32_t bOff  = (uint32_t)(((lane & 7) + ((lane >> 4) << 3)) * 144 + ((lane >> 3) & 1) * 16);
    uint32_t vOff  = (uint32_t)(((lane & 7) + ((lane >> 3) & 1) * 8) * 144 + ((lane >> 4) & 1) * 16);

    __syncthreads();

    for (int kv0 = 0; kv0 < SS; kv0 += 64) {
        #pragma unroll
        for (int i = 0; i < 2; i++) {
            int idx = tid + i * 256;
            int r = idx >> 3, c8 = idx & 7;
            size_t srow = (size_t)(rb + kv0 + r) * QSTR + h * 64 + c8 * 8;
            *(uint4*)(smem + ATT_SKH + r * 144 + c8 * 16) = *(const uint4*)(qh + srow + 1024);
            *(uint4*)(smem + ATT_SKL + r * 144 + c8 * 16) = *(const uint4*)(ql + srow + 1024);
            *(uint4*)(smem + ATT_SVH + r * 144 + c8 * 16) = *(const uint4*)(qh + srow + 2048);
            *(uint4*)(smem + ATT_SVL + r * 144 + c8 * 16) = *(const uint4*)(ql + srow + 2048);
        }
        __syncthreads();

        float s[8][4];
        #pragma unroll
        for (int i = 0; i < 8; i++)
            #pragma unroll
            for (int j = 0; j < 4; j++) s[i][j] = 0.0f;

        #pragma unroll
        for (int kc = 0; kc < 4; kc++) {
            uint32_t ah0, ah1, ah2, ah3, al0, al1, al2, al3;
            ldm_x4(ah0, ah1, ah2, ah3, aAddr + kc * 32);
            ldm_x4(al0, al1, al2, al3, aAddr + (ATT_SQL - ATT_SQH) + kc * 32);
            #pragma unroll
            for (int nh = 0; nh < 4; nh++) {
                uint32_t ba = sb + ATT_SKH + (uint32_t)(nh * 16 * 144) + bOff + kc * 32;
                uint32_t bh_[4], bl_[4];
                ldm_x4(bh_[0], bh_[1], bh_[2], bh_[3], ba);
                ldm_x4(bl_[0], bl_[1], bl_[2], bl_[3], ba + (ATT_SKL - ATT_SKH));
                #pragma unroll
                for (int o = 0; o < 2; o++) {
                    int nt = nh * 2 + o;
                    mma16816(s[nt], ah0, ah1, ah2, ah3, bh_[o * 2], bh_[o * 2 + 1]);
                    mma16816(s[nt], ah0, ah1, ah2, ah3, bl_[o * 2], bl_[o * 2 + 1]);
                    mma16816(s[nt], al0, al1, al2, al3, bh_[o * 2], bh_[o * 2 + 1]);
                }
            }
        }

        float mx0 = -1e30f, mx1 = -1e30f;
        #pragma unroll
        for (int nt = 0; nt < 8; nt++) {
            s[nt][0] *= 0.125f; s[nt][1] *= 0.125f; s[nt][2] *= 0.125f; s[nt][3] *= 0.125f;
            mx0 = fmaxf(mx0, fmaxf(s[nt][0], s[nt][1]));
            mx1 = fmaxf(mx1, fmaxf(s[nt][2], s[nt][3]));
        }
        mx0 = fmaxf(mx0, __shfl_xor_sync(0xffffffffu, mx0, 1));
        mx0 = fmaxf(mx0, __shfl_xor_sync(0xffffffffu, mx0, 2));
        mx1 = fmaxf(mx1, __shfl_xor_sync(0xffffffffu, mx1, 1));
        mx1 = fmaxf(mx1, __shfl_xor_sync(0xffffffffu, mx1, 2));
        float mn0 = fmaxf(m0, mx0), mn1 = fmaxf(m1, mx1);
        float alpha0 = __expf(m0 - mn0), alpha1 = __expf(m1 - mn1);
        m0 = mn0; m1 = mn1;
        float sum0 = 0.0f, sum1 = 0.0f;
        #pragma unroll
        for (int nt = 0; nt < 8; nt++) {
            s[nt][0] = __expf(s[nt][0] - m0);
            s[nt][1] = __expf(s[nt][1] - m0);
            s[nt][2] = __expf(s[nt][2] - m1);
            s[nt][3] = __expf(s[nt][3] - m1);
            sum0 += s[nt][0] + s[nt][1];
            sum1 += s[nt][2] + s[nt][3];
        }
        sum0 += __shfl_xor_sync(0xffffffffu, sum0, 1);
        sum0 += __shfl_xor_sync(0xffffffffu, sum0, 2);
        sum1 += __shfl_xor_sync(0xffffffffu, sum1, 1);
        sum1 += __shfl_xor_sync(0xffffffffu, sum1, 2);
        l0 = l0 * alpha0 + sum0;
        l1 = l1 * alpha1 + sum1;
        #pragma unroll
        for (int dt = 0; dt < 8; dt++) {
            accO[dt][0] *= alpha0; accO[dt][1] *= alpha0;
            accO[dt][2] *= alpha1; accO[dt][3] *= alpha1;
        }

        #pragma unroll
        for (int kc2 = 0; kc2 < 4; kc2++) {
            int n0 = kc2 * 2, n1 = kc2 * 2 + 1;
            __nv_bfloat16 h00 = __float2bfloat16(s[n0][0]), h01 = __float2bfloat16(s[n0][1]);
            __nv_bfloat16 h02 = __float2bfloat16(s[n0][2]), h03 = __float2bfloat16(s[n0][3]);
            __nv_bfloat16 h10 = __float2bfloat16(s[n1][0]), h11 = __float2bfloat16(s[n1][1]);
            __nv_bfloat16 h12 = __float2bfloat16(s[n1][2]), h13 = __float2bfloat16(s[n1][3]);
            uint32_t ph0 = (uint32_t)__bfloat16_as_ushort(h00) | ((uint32_t)__bfloat16_as_ushort(h01) << 16);
            uint32_t ph1 = (uint32_t)__bfloat16_as_ushort(h02) | ((uint32_t)__bfloat16_as_ushort(h03) << 16);
            uint32_t ph2 = (uint32_t)__bfloat16_as_ushort(h10) | ((uint32_t)__bfloat16_as_ushort(h11) << 16);
            uint32_t ph3 = (uint32_t)__bfloat16_as_ushort(h12) | ((uint32_t)__bfloat16_as_ushort(h13) << 16);
            uint32_t pl0 = pack_bf16(s[n0][0] - __bfloat162float(h00), s[n0][1] - __bfloat162float(h01));
            uint32_t pl1 = pack_bf16(s[n0][2] - __bfloat162float(h02), s[n0][3] - __bfloat162float(h03));
            uint32_t pl2 = pack_bf16(s[n1][0] - __bfloat162float(h10), s[n1][1] - __bfloat162float(h11));
            uint32_t pl3 = pack_bf16(s[n1][2] - __bfloat162float(h12), s[n1][3] - __bfloat162float(h13));
            #pragma unroll
            for (int nd = 0; nd < 4; nd++) {
                uint32_t va = sb + ATT_SVH + (uint32_t)(kc2 * 16 * 144) + vOff + nd * 32;
                uint32_t vh_[4], vl_[4];
                ldm_x4_t(vh_[0], vh_[1], vh_[2], vh_[3], va);
                ldm_x4_t(vl_[0], vl_[1], vl_[2], vl_[3], va + (ATT_SVL - ATT_SVH));
                #pragma unroll
                for (int o = 0; o < 2; o++) {
                    int dt = nd * 2 + o;
                    mma16816(accO[dt], ph0, ph1, ph2, ph3, vh_[o * 2], vh_[o * 2 + 1]);
                    mma16816(accO[dt], ph0, ph1, ph2, ph3, vl_[o * 2], vl_[o * 2 + 1]);
                    mma16816(accO[dt], pl0, pl1, pl2, pl3, vh_[o * 2], vh_[o * 2 + 1]);
                }
            }
        }
        __syncthreads();
    }

    float inv0 = 1.0f / l0, inv1 = 1.0f / l1;
    int g = lane >> 2, c2 = (lane & 3) * 2;
    int row = rb + qt * 128 + warp * 16 + g;
    int colb = h * 64 + c2;
    #pragma unroll
    for (int dt = 0; dt < 8; dt++) {
        float v0 = accO[dt][0] * inv0, v1 = accO[dt][1] * inv0;
        float v2 = accO[dt][2] * inv1, v3 = accO[dt][3] * inv1;
        __nv_bfloat16 h0 = __float2bfloat16(v0), h1 = __float2bfloat16(v1);
        __nv_bfloat16 h2 = __float2bfloat16(v2), h3 = __float2bfloat16(v3);
        uint32_t hp0 = (uint32_t)__bfloat16_as_ushort(h0) | ((uint32_t)__bfloat16_as_ushort(h1) << 16);
        uint32_t hp1 = (uint32_t)__bfloat16_as_ushort(h2) | ((uint32_t)__bfloat16_as_ushort(h3) << 16);
        int col = colb + dt * 8;
        *(uint32_t*)(oh + (size_t)row * EE + col) = hp0;
        *(uint32_t*)(oh + (size_t)(row + 8) * EE + col) = hp1;
        *(uint32_t*)(ol + (size_t)row * EE + col) =
            pack_bf16(v0 - __bfloat162float(h0), v1 - __bfloat162float(h1));
        *(uint32_t*)(ol + (size_t)(row + 8) * EE + col) =
            pack_bf16(v2 - __bfloat162float(h2), v3 - __bfloat162float(h3));
    }
}

// ---------------- fp32 -> bf16 hi/lo split -----------------------------------
__global__ __launch_bounds__(256) void split_kernel(const float* __restrict__ in,
                                                    __nv_bfloat16* __restrict__ hi,
                                                    __nv_bfloat16* __restrict__ lo,
                                                    int n4) {
    int i = blockIdx.x * 256 + threadIdx.x;
    if (i >= n4) return;
    float4 v = ((const float4*)in)[i];
    float x[4] = {v.x, v.y, v.z, v.w};
    uint32_t hw[4], lw[4];
    #pragma unroll
    for (int k = 0; k < 4; k++) {
        __nv_bfloat16 h = __float2bfloat16(x[k]);
        float rr = x[k] - __bfloat162float(h);
        __nv_bfloat16 l = __float2bfloat16(rr);
        hw[k] = (uint32_t)__bfloat16_as_ushort(h);
        lw[k] = (uint32_t)__bfloat16_as_ushort(l);
    }
    uint2 ho, loo;
    ho.x  = hw[0] | (hw[1] << 16);  ho.y  = hw[2] | (hw[3] << 16);
    loo.x = lw[0] | (lw[1] << 16);  loo.y = lw[2] | (lw[3] << 16);
    ((uint2*)hi)[i] = ho;
    ((uint2*)lo)[i] = loo;
}

// ---------------- y = LN(a + b) * g + beta (+ bf16 split) --------------------
__global__ __launch_bounds__(256) void add_ln_split_kernel(const float* __restrict__ a,
                                                           const float* __restrict__ bsrc,
                                                           const float* __restrict__ g,
                                                           const float* __restrict__ beta,
                                                           float* __restrict__ y,
                                                           __nv_bfloat16* __restrict__ yh,
                                                           __nv_bfloat16* __restrict__ yl) {
    int row = blockIdx.x;
    int tid = threadIdx.x;
    const float* ar = a + (size_t)row * EE;
    const float* br = bsrc + (size_t)row * EE;
    float v[4];
    float s = 0.0f, s2 = 0.0f;
    #pragma unroll
    for (int k = 0; k < 4; k++) {
        float t = ar[tid + 256 * k] + br[tid + 256 * k];
        v[k] = t; s += t; s2 += t * t;
    }
    __shared__ float red[18];
    #pragma unroll
    for (int off = 16; off; off >>= 1) {
        s  += __shfl_xor_sync(0xffffffffu, s,  off);
        s2 += __shfl_xor_sync(0xffffffffu, s2, off);
    }
    int wid = tid >> 5, lid = tid & 31;
    if (lid == 0) { red[wid] = s; red[wid + 8] = s2; }
    __syncthreads();
    if (tid < 32) {
        float a1 = (tid < 8) ? red[tid] : 0.0f;
        float a2 = (tid < 8) ? red[tid + 8] : 0.0f;
        #pragma unroll
        for (int off = 4; off; off >>= 1) {
            a1 += __shfl_xor_sync(0xffffffffu, a1, off);
            a2 += __shfl_xor_sync(0xffffffffu, a2, off);
        }
        if (tid == 0) { red[16] = a1; red[17] = a2; }
    }
    __syncthreads();
    float mu = red[16] * (1.0f / EE);
    float var = red[17] * (1.0f / EE) - mu * mu;
    float rs = rsqrtf(var + 1e-5f);
    float* yr = y + (size_t)row * EE;
    __nv_bfloat16* yhr = yh + (size_t)row * EE;
    __nv_bfloat16* ylr = yl + (size_t)row * EE;
    #pragma unroll
    for (int k = 0; k < 4; k++) {
        int c = tid + 256 * k;
        float val = (v[k] - mu) * rs * g[c] + beta[c];
        yr[c] = val;
        __nv_bfloat16 h = __float2bfloat16(val);
        yhr[c] = h;
        ylr[c] = __float2bfloat16(val - __bfloat162float(h));
    }
}

// ---------------- mean-pool over S -------------------------------------------
__global__ __launch_bounds__(256) void pool_kernel(const float* __restrict__ x,
                                                   float* __restrict__ pooled) {
    int idx = blockIdx.x * 256 + threadIdx.x;
    int b = idx >> 10, e = idx & 1023;
    const float* p = x + (size_t)b * SS * EE + e;
    float s = 0.0f;
    for (int sI = 0; sI < SS; sI++) s += p[(size_t)sI * EE];
    pooled[idx] = s * (1.0f / SS);
}

// ---------------- complexity estimator ---------------------------------------
__global__ __launch_bounds__(256) void ce_kernel(const float* __restrict__ pooled,
                                                 const float* __restrict__ w1,
                                                 const float* __restrict__ b1,
                                                 const float* __restrict__ w2,
                                                 const float* __restrict__ b2,
                                                 float* __restrict__ out) {
    int b = blockIdx.x, j = threadIdx.x;
    const float* p = pooled + b * EE;
    const float* w = w1 + (size_t)j * EE;
    float s = b1[j];
    for (int k = 0; k < EE; k++) s = fmaf(p[k], w[k], s);
    float h = fmaxf(s, 0.0f);
    __shared__ float red[256];
    red[j] = h * w2[j];
    __syncthreads();
    for (int off = 128; off; off >>= 1) {
        if (j < off) red[j] += red[j + off];
        __syncthreads();
    }
    if (j == 0) {
        float logit = red[0] + b2[0];
        float prob = 1.0f / (1.0f + expf(-logit));
        out[OFF_PROBS + b] = prob;
        out[OFF_MODE + b] = (prob > 0.5f) ? 1.0f : 0.0f;
    }
}

// ---------------- select + mean(mode) ----------------------------------------
__global__ __launch_bounds__(256) void finalize_kernel(const float* __restrict__ t,
                                                       const float* __restrict__ f,
                                                       float* __restrict__ out) {
    size_t i = (size_t)blockIdx.x * 256 + threadIdx.x;
    int b = (int)((i * 4) >> 20);
    float m = out[OFF_MODE + b];
    float4 r = (m > 0.5f) ? ((const float4*)t)[i] : ((const float4*)f)[i];
    ((float4*)out)[i] = r;
    if (i == 0) {
        float sAcc = 0.0f;
        for (int k = 0; k < 8; k++) sAcc += out[OFF_MODE + k];
        out[OFF_MEAN] = sAcc * 0.125f;
    }
}

// -----------------------------------------------------------------------------
extern "C" void kernel_launch(void* const* d_in, const int* in_sizes, int n_in,
                              void* d_out, int out_size) {
    const float* x      = (const float*)d_in[0];
    const float* w_in   = (const float*)d_in[1];
    const float* w_out  = (const float*)d_in[2];
    const float* ffn_w1 = (const float*)d_in[3];
    const float* ffn_w2 = (const float*)d_in[4];
    const float* ln1_g  = (const float*)d_in[5];
    const float* ln1_b  = (const float*)d_in[6];
    const float* ln2_g  = (const float*)d_in[7];
    const float* ln2_b  = (const float*)d_in[8];
    const float* ce_w1  = (const float*)d_in[9];
    const float* ce_b1  = (const float*)d_in[10];
    const float* ce_w2  = (const float*)d_in[11];
    const float* ce_b2  = (const float*)d_in[12];
    const float* fast_w = (const float*)d_in[13];
    float* out = (float*)d_out;

    float *bufA, *bufB, *bufT, *bufT1, *bufFast, *pooled;
    __nv_bfloat16 *wbh, *wbl, *ah, *al, *bh, *bl;
    cudaGetSymbolAddress((void**)&bufA, g_bufA);
    cudaGetSymbolAddress((void**)&bufB, g_bufB);
    cudaGetSymbolAddress((void**)&bufT, g_bufT);
    cudaGetSymbolAddress((void**)&bufT1, g_bufT1);
    cudaGetSymbolAddress((void**)&bufFast, g_bufFast);
    cudaGetSymbolAddress((void**)&pooled, g_pooled);
    cudaGetSymbolAddress((void**)&wbh, g_wb_hi);
    cudaGetSymbolAddress((void**)&wbl, g_wb_lo);
    cudaGetSymbolAddress((void**)&ah, g_actA_hi);
    cudaGetSymbolAddress((void**)&al, g_actA_lo);
    cudaGetSymbolAddress((void**)&bh, g_actB_hi);
    cudaGetSymbolAddress((void**)&bl, g_actB_lo);

    cudaFuncSetAttribute(mma_gemm<0>, cudaFuncAttributeMaxDynamicSharedMemorySize, SMT);
    cudaFuncSetAttribute(mma_gemm<1>, cudaFuncAttributeMaxDynamicSharedMemorySize, SMT);
    cudaFuncSetAttribute(mma_gemm<2>, cudaFuncAttributeMaxDynamicSharedMemorySize, SMT);
    cudaFuncSetAttribute(mma_gemm<3>, cudaFuncAttributeMaxDynamicSharedMemorySize, SMT);
    cudaFuncSetAttribute(attn_mma, cudaFuncAttributeMaxDynamicSharedMemorySize, ATT_SMEM);

    // weight splits
    split_kernel<<<(2*3*EE*EE/4)/256, 256>>>(w_in,   wbh + OW_IN,   wbl + OW_IN,   2*3*EE*EE/4);
    split_kernel<<<(2*EE*EE/4)/256,   256>>>(w_out,  wbh + OW_OUT,  wbl + OW_OUT,  2*EE*EE/4);
    split_kernel<<<(2*4*EE*EE/4)/256, 256>>>(ffn_w1, wbh + OW_F1,   wbl + OW_F1,   2*4*EE*EE/4);
    split_kernel<<<(2*4*EE*EE/4)/256, 256>>>(ffn_w2, wbh + OW_F2,   wbl + OW_F2,   2*4*EE*EE/4);
    split_kernel<<<(EE*EE/4)/256,     256>>>(fast_w, wbh + OW_FAST, wbl + OW_FAST, EE*EE/4);

    // complexity estimator
    pool_kernel<<<(BB * EE) / 256, 256>>>(x, pooled);
    ce_kernel<<<BB, 256>>>(pooled, ce_w1, ce_b1, ce_w2, ce_b2, out);

    // split x -> A (serves fast path + layer-0 qkv)
    split_kernel<<<(MROWS*EE/4)/256, 256>>>(x, ah, al, MROWS*EE/4);

    // fast path: gelu(x @ fast_w^T) -> fp32
    mma_gemm<1><<<dim3(EE/128, MROWS/128), 256, SMT>>>(
        ah, al, wbh + OW_FAST, wbl + OW_FAST, bufFast, nullptr, nullptr, EE, EE);

    // thinking path
    const float* tin = x;
    for (int l = 0; l < LL; l++) {
        mma_gemm<2><<<dim3(3*EE/128, MROWS/128), 256, SMT>>>(
            ah, al, wbh + OW_IN + (size_t)l*3*EE*EE, wbl + OW_IN + (size_t)l*3*EE*EE,
            nullptr, bh, bl, 3*EE, EE);
        attn_mma<<<dim3(SS/128, HH, BB), 256, ATT_SMEM>>>(bh, bl, ah, al);
        mma_gemm<0><<<dim3(EE/128, MROWS/128), 256, SMT>>>(
            ah, al, wbh + OW_OUT + (size_t)l*EE*EE, wbl + OW_OUT + (size_t)l*EE*EE,
            bufA, nullptr, nullptr, EE, EE);
        add_ln_split_kernel<<<MROWS, 256>>>(tin, bufA, ln1_g + l*EE, ln1_b + l*EE,
                                            bufT1, ah, al);
        mma_gemm<3><<<dim3(4*EE/128, MROWS/128), 256, SMT>>>(
            ah, al, wbh + OW_F1 + (size_t)l*4*EE*EE, wbl + OW_F1 + (size_t)l*4*EE*EE,
            nullptr, bh, bl, 4*EE, EE);
        mma_gemm<0><<<dim3(EE/128, MROWS/128), 256, SMT>>>(
            bh, bl, wbh + OW_F2 + (size_t)l*4*EE*EE, wbl + OW_F2 + (size_t)l*4*EE*EE,
            bufB, nullptr, nullptr, EE, 4*EE);
        add_ln_split_kernel<<<MROWS, 256>>>(bufT1, bufB, ln2_g + l*EE, ln2_b + l*EE,
                                            bufT, ah, al);
        tin = bufT;
    }

    finalize_kernel<<<(MROWS * EE / 4) / 256, 256>>>(bufT, bufFast, out);
}